// round 5
// baseline (speedup 1.0000x reference)
#include <cuda_runtime.h>
#include <cstdint>

// Problem constants
#define B_DIM 32
#define N_DIM 2048
#define F_DIM 512          // NUM_FEATURE
#define K_DIM 256          // NUM_CLUSTER
#define D_DIM 1024         // D_MODEL
#define M_FEAT (B_DIM * N_DIM)   // 65536 rows for the big GEMM
#define LN_EPS 1e-5f
#define NEG_SLOPE 0.2f

// Scratch for the city embedding c[n, d] (8 MB, static device array — no runtime alloc)
__device__ float g_c[N_DIM * D_DIM];

// ---------------------------------------------------------------------------
// tf32 helpers
// ---------------------------------------------------------------------------
__device__ __forceinline__ uint32_t f2tf32(float x) {
    uint32_t y;
    asm("cvt.rna.tf32.f32 %0, %1;" : "=r"(y) : "f"(x));
    return y;
}

// m16n8k4 tf32 MMA: D = A(16x4,row) * B(4x8,col) + C
// Per-thread fragments (lane g = lane>>2, tig = lane&3):
//   a0 = A[g][tig], a1 = A[g+8][tig]
//   b0 = B[tig][g]
//   c0 = C[g][2*tig], c1 = C[g][2*tig+1], c2 = C[g+8][2*tig], c3 = C[g+8][2*tig+1]
__device__ __forceinline__ void mma_tf32_k4(float (&c)[4], uint32_t a0, uint32_t a1, uint32_t b0) {
    asm volatile(
        "mma.sync.aligned.m16n8k4.row.col.f32.tf32.tf32.f32 "
        "{%0,%1,%2,%3}, {%4,%5}, {%6}, {%0,%1,%2,%3};\n"
        : "+f"(c[0]), "+f"(c[1]), "+f"(c[2]), "+f"(c[3])
        : "r"(a0), "r"(a1), "r"(b0));
}

// ---------------------------------------------------------------------------
// Tiled tf32 GEMM:  out[m, d] = epilogue( sum_k A[m,k] * W[d,k] + bias[d] )
//   Block tile: 128 (m) x 128 (d), k-tile 16, 256 threads = 8 warps (4m x 2n),
//   warp tile 32 (m) x 64 (d), per-thread 2x8 fragments of m16n8.
//   FEAT=true : epilogue = leaky_relu(v) * g_c[m % 2048][d], write to out
//   FEAT=false: epilogue = v, write to g_c
// ---------------------------------------------------------------------------
template <int KDIM, int KT, bool FEAT>
__global__ void __launch_bounds__(256, 2)
gemm_tf32_kernel(const float* __restrict__ A,
                 const float* __restrict__ W,
                 const float* __restrict__ bias,
                 float* __restrict__ out)
{
    // +4 padding: stride 20 words -> (row*20 + col) hits 32 distinct banks
    // for the 8-row x 4-col fragment-load pattern (conflict-free).
    __shared__ uint32_t As[2][128][20];
    __shared__ uint32_t Bs[2][128][20];

    const int tid  = threadIdx.x;
    const int lane = tid & 31;
    const int warp = tid >> 5;
    const int wm   = warp & 3;   // 0..3  (m direction)
    const int wn   = warp >> 2;  // 0..1  (d direction)
    const int g    = lane >> 2;  // 0..7
    const int tig  = lane & 3;   // 0..3

    const int blockM = blockIdx.y * 128;
    const int blockN = blockIdx.x * 128;

    // Staging: 512 float4 per 128x16 tile; each thread handles float4 #tid and #tid+256.
    const int sr0 = tid >> 2;        // row 0..63 (second chunk: +64)
    const int sc0 = (tid & 3) * 4;   // k column (in floats)

    const float* Abase = A + (size_t)(blockM + sr0) * KDIM + sc0;
    const float* Wbase = W + (size_t)(blockN + sr0) * KDIM + sc0;

    float4 pa0, pa1, pb0, pb1;

    auto load_tile = [&](int kt) {
        const float* ap = Abase + kt * 16;
        const float* wp = Wbase + kt * 16;
        pa0 = *(const float4*)ap;
        pa1 = *(const float4*)(ap + (size_t)64 * KDIM);
        pb0 = *(const float4*)wp;
        pb1 = *(const float4*)(wp + (size_t)64 * KDIM);
    };
    auto store_tile = [&](int buf) {
        uint4 u;
        u.x = f2tf32(pa0.x); u.y = f2tf32(pa0.y); u.z = f2tf32(pa0.z); u.w = f2tf32(pa0.w);
        *(uint4*)&As[buf][sr0][sc0] = u;
        u.x = f2tf32(pa1.x); u.y = f2tf32(pa1.y); u.z = f2tf32(pa1.z); u.w = f2tf32(pa1.w);
        *(uint4*)&As[buf][sr0 + 64][sc0] = u;
        u.x = f2tf32(pb0.x); u.y = f2tf32(pb0.y); u.z = f2tf32(pb0.z); u.w = f2tf32(pb0.w);
        *(uint4*)&Bs[buf][sr0][sc0] = u;
        u.x = f2tf32(pb1.x); u.y = f2tf32(pb1.y); u.z = f2tf32(pb1.z); u.w = f2tf32(pb1.w);
        *(uint4*)&Bs[buf][sr0 + 64][sc0] = u;
    };

    float acc[2][8][4];
#pragma unroll
    for (int mt = 0; mt < 2; ++mt)
#pragma unroll
        for (int nt = 0; nt < 8; ++nt)
#pragma unroll
            for (int i = 0; i < 4; ++i) acc[mt][nt][i] = 0.0f;

    load_tile(0);
    store_tile(0);
    __syncthreads();

    for (int kt = 0; kt < KT; ++kt) {
        const int cur = kt & 1;
        if (kt + 1 < KT) load_tile(kt + 1);   // prefetch next tile into registers

#pragma unroll
        for (int ks = 0; ks < 4; ++ks) {
            const int k0 = ks * 4 + tig;
            uint32_t af[2][2];
#pragma unroll
            for (int mt = 0; mt < 2; ++mt) {
                const int r = wm * 32 + mt * 16 + g;
                af[mt][0] = As[cur][r][k0];
                af[mt][1] = As[cur][r + 8][k0];
            }
            uint32_t bf[8];
#pragma unroll
            for (int nt = 0; nt < 8; ++nt)
                bf[nt] = Bs[cur][wn * 64 + nt * 8 + g][k0];

#pragma unroll
            for (int mt = 0; mt < 2; ++mt)
#pragma unroll
                for (int nt = 0; nt < 8; ++nt)
                    mma_tf32_k4(acc[mt][nt], af[mt][0], af[mt][1], bf[nt]);
        }

        if (kt + 1 < KT) store_tile(cur ^ 1);
        __syncthreads();
    }

    // Epilogue
#pragma unroll
    for (int mt = 0; mt < 2; ++mt) {
        const int m0 = blockM + wm * 32 + mt * 16 + g;
#pragma unroll
        for (int nt = 0; nt < 8; ++nt) {
            const int d0 = blockN + wn * 64 + nt * 8 + 2 * tig;
            const float bs0 = bias[d0];
            const float bs1 = bias[d0 + 1];

            float v00 = acc[mt][nt][0] + bs0;
            float v01 = acc[mt][nt][1] + bs1;
            float v10 = acc[mt][nt][2] + bs0;
            float v11 = acc[mt][nt][3] + bs1;

            if (FEAT) {
                v00 = (v00 >= 0.0f) ? v00 : NEG_SLOPE * v00;
                v01 = (v01 >= 0.0f) ? v01 : NEG_SLOPE * v01;
                v10 = (v10 >= 0.0f) ? v10 : NEG_SLOPE * v10;
                v11 = (v11 >= 0.0f) ? v11 : NEG_SLOPE * v11;
                const float* gr0 = g_c + (size_t)(m0 & (N_DIM - 1)) * D_DIM;
                const float* gr1 = g_c + (size_t)((m0 + 8) & (N_DIM - 1)) * D_DIM;
                v00 *= gr0[d0]; v01 *= gr0[d0 + 1];
                v10 *= gr1[d0]; v11 *= gr1[d0 + 1];
                float2* o0 = (float2*)(out + (size_t)m0 * D_DIM + d0);
                float2* o1 = (float2*)(out + (size_t)(m0 + 8) * D_DIM + d0);
                *o0 = make_float2(v00, v01);
                *o1 = make_float2(v10, v11);
            } else {
                float2* o0 = (float2*)(g_c + (size_t)m0 * D_DIM + d0);
                float2* o1 = (float2*)(g_c + (size_t)(m0 + 8) * D_DIM + d0);
                *o0 = make_float2(v00, v01);
                *o1 = make_float2(v10, v11);
            }
        }
    }
}

// ---------------------------------------------------------------------------
// In-place LayerNorm over D=1024, one block (256 threads, float4) per row.
// ---------------------------------------------------------------------------
__global__ void __launch_bounds__(256)
ln_kernel(float* __restrict__ x,
          const float* __restrict__ gamma,
          const float* __restrict__ beta)
{
    __shared__ float rs[8], rq[8];
    const int row = blockIdx.x;
    const int t = threadIdx.x;

    float4* xr = (float4*)(x + (size_t)row * D_DIM);
    float4 v = xr[t];

    float s = v.x + v.y + v.z + v.w;
    float q = v.x * v.x + v.y * v.y + v.z * v.z + v.w * v.w;

#pragma unroll
    for (int off = 16; off >= 1; off >>= 1) {
        s += __shfl_xor_sync(0xffffffffu, s, off);
        q += __shfl_xor_sync(0xffffffffu, q, off);
    }
    if ((t & 31) == 0) { rs[t >> 5] = s; rq[t >> 5] = q; }
    __syncthreads();

    s = 0.0f; q = 0.0f;
#pragma unroll
    for (int i = 0; i < 8; ++i) { s += rs[i]; q += rq[i]; }

    const float mean = s * (1.0f / D_DIM);
    const float var  = q * (1.0f / D_DIM) - mean * mean;
    const float rstd = rsqrtf(var + LN_EPS);

    const float4 gg = ((const float4*)gamma)[t];
    const float4 bb = ((const float4*)beta)[t];

    v.x = (v.x - mean) * rstd * gg.x + bb.x;
    v.y = (v.y - mean) * rstd * gg.y + bb.y;
    v.z = (v.z - mean) * rstd * gg.z + bb.z;
    v.w = (v.w - mean) * rstd * gg.w + bb.w;
    xr[t] = v;
}

// ---------------------------------------------------------------------------
// Launch: 3 kernels, same stream, fully graph-capturable, no allocations.
// ---------------------------------------------------------------------------
extern "C" void kernel_launch(void* const* d_in, const int* in_sizes, int n_in,
                              void* d_out, int out_size)
{
    const float* input  = (const float*)d_in[0];  // [B, N, 512]
    const float* statc  = (const float*)d_in[1];  // [N, 256]
    const float* W_feat = (const float*)d_in[2];  // [1024, 512]
    const float* b_feat = (const float*)d_in[3];  // [1024]
    const float* W_city = (const float*)d_in[4];  // [1024, 256]
    const float* b_city = (const float*)d_in[5];  // [1024]
    const float* gamma  = (const float*)d_in[6];  // [1024]
    const float* beta   = (const float*)d_in[7];  // [1024]
    float* out = (float*)d_out;                   // [B, N, 1024]

    // 1) city embed: g_c[n,d] = static · W_city^T + b_city   (KDIM=256, KT=16)
    gemm_tf32_kernel<K_DIM, K_DIM / 16, false>
        <<<dim3(D_DIM / 128, N_DIM / 128), 256>>>(statc, W_city, b_city, nullptr);

    // 2) feat embed + leaky + gate -> out  (KDIM=512, KT=32)
    //    blockIdx.x = d-block (fast) so a wave of CTAs reuses input rows in L2.
    gemm_tf32_kernel<F_DIM, F_DIM / 16, true>
        <<<dim3(D_DIM / 128, M_FEAT / 128), 256>>>(input, W_feat, b_feat, out);

    // 3) in-place LayerNorm on out
    ln_kernel<<<M_FEAT, 256>>>(out, gamma, beta);
}

// round 11
// speedup vs baseline: 1.1144x; 1.1144x over previous
#include <cuda_runtime.h>
#include <cstdint>

// Problem constants
#define B_DIM 32
#define N_DIM 2048
#define F_DIM 512          // NUM_FEATURE
#define K_DIM 256          // NUM_CLUSTER
#define D_DIM 1024         // D_MODEL
#define M_FEAT (B_DIM * N_DIM)   // 65536 rows for the big GEMM
#define LN_EPS 1e-5f
#define NEG_SLOPE 0.2f

// Scratch for the city embedding c[n, d] (8 MB, static device array)
__device__ float g_c[N_DIM * D_DIM];

// ---------------------------------------------------------------------------
// tf32 helpers (legacy mma.sync path only — tcgen05 is rejected by this
// build's ptxas target, which lacks the 'a' feature suffix)
// ---------------------------------------------------------------------------
__device__ __forceinline__ uint32_t f2tf32(float x) {
    uint32_t y;
    asm("cvt.rna.tf32.f32 %0, %1;" : "=r"(y) : "f"(x));
    return y;
}

// m16n8k8 tf32 MMA (row.col):
//   a0=(g,tig) a1=(g+8,tig) a2=(g,tig+4) a3=(g+8,tig+4)
//   b0=(tig,g) b1=(tig+4,g)
//   c0=(g,2tig) c1=(g,2tig+1) c2=(g+8,2tig) c3=(g+8,2tig+1)
__device__ __forceinline__ void mma_tf32_k8(float (&c)[4], const uint32_t (&a)[4],
                                            const uint32_t (&b)[2]) {
    asm volatile(
        "mma.sync.aligned.m16n8k8.row.col.f32.tf32.tf32.f32 "
        "{%0,%1,%2,%3}, {%4,%5,%6,%7}, {%8,%9}, {%0,%1,%2,%3};\n"
        : "+f"(c[0]), "+f"(c[1]), "+f"(c[2]), "+f"(c[3])
        : "r"(a[0]), "r"(a[1]), "r"(a[2]), "r"(a[3]), "r"(b[0]), "r"(b[1]));
}

// ---------------------------------------------------------------------------
// Tiled tf32 GEMM:  out[m, d] = epilogue( sum_k A[m,k] * W[d,k] + bias[d] )
//   Block tile: 128 (m) x 128 (d), k-tile 16, 256 threads = 8 warps.
//   Warp tile 64 (m) x 32 (d): wm = warp&1, wn = warp>>1.
//   Per-thread: acc[4][4][4] (m16n8 tiles), k8 MMAs -> 32 MMA + 48 LDS / k16.
//   FEAT=true : epilogue = leaky_relu(v + bias) * g_c[m % 2048][d] -> out
//   FEAT=false: epilogue = v + bias -> g_c
// ---------------------------------------------------------------------------
template <int KDIM, bool FEAT>
__global__ void __launch_bounds__(256, 2)
gemm_tf32_kernel(const float* __restrict__ A,
                 const float* __restrict__ W,
                 const float* __restrict__ bias,
                 float* __restrict__ out)
{
    // stride 20 words: (20*g + tig) % 32 covers all 32 banks for the
    // 8-row x 4-col fragment-load pattern -> conflict-free (verified in R4).
    __shared__ uint32_t As[2][128][20];
    __shared__ uint32_t Bs[2][128][20];

    const int tid  = threadIdx.x;
    const int lane = tid & 31;
    const int warp = tid >> 5;
    const int wm   = warp & 1;   // m direction (x64)
    const int wn   = warp >> 1;  // d direction (x32)
    const int g    = lane >> 2;  // 0..7
    const int tig  = lane & 3;   // 0..3

    const int blockM = blockIdx.y * 128;
    const int blockN = blockIdx.x * 128;

    // Staging: each thread loads float4 rows sr0 and sr0+64 of A and B tiles.
    const int sr0 = tid >> 2;        // 0..63
    const int sc0 = (tid & 3) * 4;   // k column (floats)

    const float* Abase = A + (size_t)(blockM + sr0) * KDIM + sc0;
    const float* Wbase = W + (size_t)(blockN + sr0) * KDIM + sc0;

    float4 pa0, pa1, pb0, pb1;

    auto load_tile = [&](int kt) {
        const float* ap = Abase + kt * 16;
        const float* wp = Wbase + kt * 16;
        pa0 = *(const float4*)ap;
        pa1 = *(const float4*)(ap + (size_t)64 * KDIM);
        pb0 = *(const float4*)wp;
        pb1 = *(const float4*)(wp + (size_t)64 * KDIM);
    };
    auto store_tile = [&](int buf) {
        uint4 u;
        u.x = f2tf32(pa0.x); u.y = f2tf32(pa0.y); u.z = f2tf32(pa0.z); u.w = f2tf32(pa0.w);
        *(uint4*)&As[buf][sr0][sc0] = u;
        u.x = f2tf32(pa1.x); u.y = f2tf32(pa1.y); u.z = f2tf32(pa1.z); u.w = f2tf32(pa1.w);
        *(uint4*)&As[buf][sr0 + 64][sc0] = u;
        u.x = f2tf32(pb0.x); u.y = f2tf32(pb0.y); u.z = f2tf32(pb0.z); u.w = f2tf32(pb0.w);
        *(uint4*)&Bs[buf][sr0][sc0] = u;
        u.x = f2tf32(pb1.x); u.y = f2tf32(pb1.y); u.z = f2tf32(pb1.z); u.w = f2tf32(pb1.w);
        *(uint4*)&Bs[buf][sr0 + 64][sc0] = u;
    };

    float acc[4][4][4];
#pragma unroll
    for (int mt = 0; mt < 4; ++mt)
#pragma unroll
        for (int nt = 0; nt < 4; ++nt)
#pragma unroll
            for (int i = 0; i < 4; ++i) acc[mt][nt][i] = 0.0f;

    load_tile(0);
    store_tile(0);
    __syncthreads();

    const int KT = KDIM / 16;
    for (int kt = 0; kt < KT; ++kt) {
        const int cur = kt & 1;
        if (kt + 1 < KT) load_tile(kt + 1);   // prefetch next tile into registers

#pragma unroll
        for (int ks = 0; ks < 2; ++ks) {      // two k8 groups per k16 tile
            const int k0 = ks * 8;
            uint32_t af[4][4];
#pragma unroll
            for (int mt = 0; mt < 4; ++mt) {
                const int r = wm * 64 + mt * 16 + g;
                af[mt][0] = As[cur][r][k0 + tig];
                af[mt][1] = As[cur][r + 8][k0 + tig];
                af[mt][2] = As[cur][r][k0 + tig + 4];
                af[mt][3] = As[cur][r + 8][k0 + tig + 4];
            }
            uint32_t bf[4][2];
#pragma unroll
            for (int nt = 0; nt < 4; ++nt) {
                const int rB = wn * 32 + nt * 8 + g;
                bf[nt][0] = Bs[cur][rB][k0 + tig];
                bf[nt][1] = Bs[cur][rB][k0 + tig + 4];
            }
#pragma unroll
            for (int mt = 0; mt < 4; ++mt)
#pragma unroll
                for (int nt = 0; nt < 4; ++nt)
                    mma_tf32_k8(acc[mt][nt], af[mt], bf[nt]);
        }

        if (kt + 1 < KT) store_tile(cur ^ 1);
        __syncthreads();
    }

    // Epilogue
#pragma unroll
    for (int mt = 0; mt < 4; ++mt) {
        const int m0 = blockM + wm * 64 + mt * 16 + g;
#pragma unroll
        for (int nt = 0; nt < 4; ++nt) {
            const int d0 = blockN + wn * 32 + nt * 8 + 2 * tig;
            const float bs0 = bias[d0];
            const float bs1 = bias[d0 + 1];

            float v00 = acc[mt][nt][0] + bs0;
            float v01 = acc[mt][nt][1] + bs1;
            float v10 = acc[mt][nt][2] + bs0;
            float v11 = acc[mt][nt][3] + bs1;

            if (FEAT) {
                v00 = (v00 >= 0.0f) ? v00 : NEG_SLOPE * v00;
                v01 = (v01 >= 0.0f) ? v01 : NEG_SLOPE * v01;
                v10 = (v10 >= 0.0f) ? v10 : NEG_SLOPE * v10;
                v11 = (v11 >= 0.0f) ? v11 : NEG_SLOPE * v11;
                const float* gr0 = g_c + (size_t)(m0 & (N_DIM - 1)) * D_DIM;
                const float* gr1 = g_c + (size_t)((m0 + 8) & (N_DIM - 1)) * D_DIM;
                v00 *= gr0[d0]; v01 *= gr0[d0 + 1];
                v10 *= gr1[d0]; v11 *= gr1[d0 + 1];
                float2* o0 = (float2*)(out + (size_t)m0 * D_DIM + d0);
                float2* o1 = (float2*)(out + (size_t)(m0 + 8) * D_DIM + d0);
                *o0 = make_float2(v00, v01);
                *o1 = make_float2(v10, v11);
            } else {
                float2* o0 = (float2*)(g_c + (size_t)m0 * D_DIM + d0);
                float2* o1 = (float2*)(g_c + (size_t)(m0 + 8) * D_DIM + d0);
                *o0 = make_float2(v00, v01);
                *o1 = make_float2(v10, v11);
            }
        }
    }
}

// ---------------------------------------------------------------------------
// In-place LayerNorm over D=1024, one block (256 threads, float4) per row.
// ---------------------------------------------------------------------------
__global__ void __launch_bounds__(256)
ln_kernel(float* __restrict__ x,
          const float* __restrict__ gamma,
          const float* __restrict__ beta)
{
    __shared__ float rs[8], rq[8];
    const int row = blockIdx.x;
    const int t = threadIdx.x;

    float4* xr = (float4*)(x + (size_t)row * D_DIM);
    float4 v = xr[t];

    float s = v.x + v.y + v.z + v.w;
    float q = v.x * v.x + v.y * v.y + v.z * v.z + v.w * v.w;

#pragma unroll
    for (int off = 16; off >= 1; off >>= 1) {
        s += __shfl_xor_sync(0xffffffffu, s, off);
        q += __shfl_xor_sync(0xffffffffu, q, off);
    }
    if ((t & 31) == 0) { rs[t >> 5] = s; rq[t >> 5] = q; }
    __syncthreads();

    s = 0.0f; q = 0.0f;
#pragma unroll
    for (int i = 0; i < 8; ++i) { s += rs[i]; q += rq[i]; }

    const float mean = s * (1.0f / D_DIM);
    const float var  = q * (1.0f / D_DIM) - mean * mean;
    const float rstd = rsqrtf(var + LN_EPS);

    const float4 gg = ((const float4*)gamma)[t];
    const float4 bb = ((const float4*)beta)[t];

    v.x = (v.x - mean) * rstd * gg.x + bb.x;
    v.y = (v.y - mean) * rstd * gg.y + bb.y;
    v.z = (v.z - mean) * rstd * gg.z + bb.z;
    v.w = (v.w - mean) * rstd * gg.w + bb.w;
    xr[t] = v;
}

// ---------------------------------------------------------------------------
// Launch: 3 kernels, same stream, graph-capturable, no allocations.
// ---------------------------------------------------------------------------
extern "C" void kernel_launch(void* const* d_in, const int* in_sizes, int n_in,
                              void* d_out, int out_size)
{
    const float* input  = (const float*)d_in[0];  // [B, N, 512]
    const float* statc  = (const float*)d_in[1];  // [N, 256]
    const float* W_feat = (const float*)d_in[2];  // [1024, 512]
    const float* b_feat = (const float*)d_in[3];  // [1024]
    const float* W_city = (const float*)d_in[4];  // [1024, 256]
    const float* b_city = (const float*)d_in[5];  // [1024]
    const float* gamma  = (const float*)d_in[6];  // [1024]
    const float* beta   = (const float*)d_in[7];  // [1024]
    float* out = (float*)d_out;                   // [B, N, 1024]

    // 1) city embed -> g_c   (K=256)
    gemm_tf32_kernel<K_DIM, false>
        <<<dim3(D_DIM / 128, N_DIM / 128), 256>>>(statc, W_city, b_city, nullptr);

    // 2) feat embed + leaky + gate -> out  (K=512)
    //    blockIdx.x = d-block (fast) so a wave of CTAs reuses input rows in L2.
    gemm_tf32_kernel<F_DIM, true>
        <<<dim3(D_DIM / 128, M_FEAT / 128), 256>>>(input, W_feat, b_feat, out);

    // 3) in-place LayerNorm on out
    ln_kernel<<<M_FEAT, 256>>>(out, gamma, beta);
}

// round 12
// speedup vs baseline: 1.1165x; 1.0019x over previous
#include <cuda_runtime.h>
#include <cstdint>

// Problem constants
#define B_DIM 32
#define N_DIM 2048
#define F_DIM 512          // NUM_FEATURE
#define K_DIM 256          // NUM_CLUSTER
#define D_DIM 1024         // D_MODEL
#define M_FEAT (B_DIM * N_DIM)   // 65536 rows for the big GEMM
#define LN_EPS 1e-5f
#define NEG_SLOPE 0.2f

// Scratch for the city embedding c[n, d] (8 MB, static device array)
__device__ float g_c[N_DIM * D_DIM];

// ---------------------------------------------------------------------------
// tf32 helpers (legacy mma.sync path only — tcgen05 is rejected by this
// build's ptxas target, which lacks the 'a' feature suffix)
// ---------------------------------------------------------------------------
__device__ __forceinline__ uint32_t f2tf32(float x) {
    uint32_t y;
    asm("cvt.rna.tf32.f32 %0, %1;" : "=r"(y) : "f"(x));
    return y;
}

// m16n8k8 tf32 MMA (row.col):
//   a0=(g,tig) a1=(g+8,tig) a2=(g,tig+4) a3=(g+8,tig+4)
//   b0=(tig,g) b1=(tig+4,g)
//   c0=(g,2tig) c1=(g,2tig+1) c2=(g+8,2tig) c3=(g+8,2tig+1)
__device__ __forceinline__ void mma_tf32_k8(float (&c)[4], const uint32_t (&a)[4],
                                            const uint32_t (&b)[2]) {
    asm volatile(
        "mma.sync.aligned.m16n8k8.row.col.f32.tf32.tf32.f32 "
        "{%0,%1,%2,%3}, {%4,%5,%6,%7}, {%8,%9}, {%0,%1,%2,%3};\n"
        : "+f"(c[0]), "+f"(c[1]), "+f"(c[2]), "+f"(c[3])
        : "r"(a[0]), "r"(a[1]), "r"(a[2]), "r"(a[3]), "r"(b[0]), "r"(b[1]));
}

// ---------------------------------------------------------------------------
// Tiled tf32 GEMM:  out[m, d] = epilogue( sum_k A[m,k] * W[d,k] + bias[d] )
//   Block tile: 128 (m) x 128 (d), k-tile 16, 256 threads = 8 warps.
//   Warp tile 64 (m) x 32 (d): wm = warp&1, wn = warp>>1.
//   Per-thread: acc[4][4][4] (m16n8 tiles), k8 MMAs -> 32 MMA + 48 LDS / k16.
//   FEAT=true : epilogue = leaky_relu(v + bias) * g_c[m % 2048][d] -> out
//   FEAT=false: epilogue = v + bias -> g_c
// ---------------------------------------------------------------------------
template <int KDIM, bool FEAT>
__global__ void __launch_bounds__(256, 2)
gemm_tf32_kernel(const float* __restrict__ A,
                 const float* __restrict__ W,
                 const float* __restrict__ bias,
                 float* __restrict__ out)
{
    // stride 20 words: (20*g + tig) % 32 covers all 32 banks for the
    // 8-row x 4-col fragment-load pattern -> conflict-free (verified in R4).
    __shared__ uint32_t As[2][128][20];
    __shared__ uint32_t Bs[2][128][20];

    const int tid  = threadIdx.x;
    const int lane = tid & 31;
    const int warp = tid >> 5;
    const int wm   = warp & 1;   // m direction (x64)
    const int wn   = warp >> 1;  // d direction (x32)
    const int g    = lane >> 2;  // 0..7
    const int tig  = lane & 3;   // 0..3

    const int blockM = blockIdx.y * 128;
    const int blockN = blockIdx.x * 128;

    // Staging: each thread loads float4 rows sr0 and sr0+64 of A and B tiles.
    const int sr0 = tid >> 2;        // 0..63
    const int sc0 = (tid & 3) * 4;   // k column (floats)

    const float* Abase = A + (size_t)(blockM + sr0) * KDIM + sc0;
    const float* Wbase = W + (size_t)(blockN + sr0) * KDIM + sc0;

    float4 pa0, pa1, pb0, pb1;

    auto load_tile = [&](int kt) {
        const float* ap = Abase + kt * 16;
        const float* wp = Wbase + kt * 16;
        pa0 = *(const float4*)ap;
        pa1 = *(const float4*)(ap + (size_t)64 * KDIM);
        pb0 = *(const float4*)wp;
        pb1 = *(const float4*)(wp + (size_t)64 * KDIM);
    };
    auto store_tile = [&](int buf) {
        uint4 u;
        u.x = f2tf32(pa0.x); u.y = f2tf32(pa0.y); u.z = f2tf32(pa0.z); u.w = f2tf32(pa0.w);
        *(uint4*)&As[buf][sr0][sc0] = u;
        u.x = f2tf32(pa1.x); u.y = f2tf32(pa1.y); u.z = f2tf32(pa1.z); u.w = f2tf32(pa1.w);
        *(uint4*)&As[buf][sr0 + 64][sc0] = u;
        u.x = f2tf32(pb0.x); u.y = f2tf32(pb0.y); u.z = f2tf32(pb0.z); u.w = f2tf32(pb0.w);
        *(uint4*)&Bs[buf][sr0][sc0] = u;
        u.x = f2tf32(pb1.x); u.y = f2tf32(pb1.y); u.z = f2tf32(pb1.z); u.w = f2tf32(pb1.w);
        *(uint4*)&Bs[buf][sr0 + 64][sc0] = u;
    };

    float acc[4][4][4];
#pragma unroll
    for (int mt = 0; mt < 4; ++mt)
#pragma unroll
        for (int nt = 0; nt < 4; ++nt)
#pragma unroll
            for (int i = 0; i < 4; ++i) acc[mt][nt][i] = 0.0f;

    load_tile(0);
    store_tile(0);
    __syncthreads();

    const int KT = KDIM / 16;
    for (int kt = 0; kt < KT; ++kt) {
        const int cur = kt & 1;
        if (kt + 1 < KT) load_tile(kt + 1);   // prefetch next tile into registers

#pragma unroll
        for (int ks = 0; ks < 2; ++ks) {      // two k8 groups per k16 tile
            const int k0 = ks * 8;
            uint32_t af[4][4];
#pragma unroll
            for (int mt = 0; mt < 4; ++mt) {
                const int r = wm * 64 + mt * 16 + g;
                af[mt][0] = As[cur][r][k0 + tig];
                af[mt][1] = As[cur][r + 8][k0 + tig];
                af[mt][2] = As[cur][r][k0 + tig + 4];
                af[mt][3] = As[cur][r + 8][k0 + tig + 4];
            }
            uint32_t bf[4][2];
#pragma unroll
            for (int nt = 0; nt < 4; ++nt) {
                const int rB = wn * 32 + nt * 8 + g;
                bf[nt][0] = Bs[cur][rB][k0 + tig];
                bf[nt][1] = Bs[cur][rB][k0 + tig + 4];
            }
#pragma unroll
            for (int mt = 0; mt < 4; ++mt)
#pragma unroll
                for (int nt = 0; nt < 4; ++nt)
                    mma_tf32_k8(acc[mt][nt], af[mt], bf[nt]);
        }

        if (kt + 1 < KT) store_tile(cur ^ 1);
        __syncthreads();
    }

    // Epilogue
#pragma unroll
    for (int mt = 0; mt < 4; ++mt) {
        const int m0 = blockM + wm * 64 + mt * 16 + g;
#pragma unroll
        for (int nt = 0; nt < 4; ++nt) {
            const int d0 = blockN + wn * 32 + nt * 8 + 2 * tig;
            const float bs0 = bias[d0];
            const float bs1 = bias[d0 + 1];

            float v00 = acc[mt][nt][0] + bs0;
            float v01 = acc[mt][nt][1] + bs1;
            float v10 = acc[mt][nt][2] + bs0;
            float v11 = acc[mt][nt][3] + bs1;

            if (FEAT) {
                v00 = (v00 >= 0.0f) ? v00 : NEG_SLOPE * v00;
                v01 = (v01 >= 0.0f) ? v01 : NEG_SLOPE * v01;
                v10 = (v10 >= 0.0f) ? v10 : NEG_SLOPE * v10;
                v11 = (v11 >= 0.0f) ? v11 : NEG_SLOPE * v11;
                const float* gr0 = g_c + (size_t)(m0 & (N_DIM - 1)) * D_DIM;
                const float* gr1 = g_c + (size_t)((m0 + 8) & (N_DIM - 1)) * D_DIM;
                v00 *= gr0[d0]; v01 *= gr0[d0 + 1];
                v10 *= gr1[d0]; v11 *= gr1[d0 + 1];
                float2* o0 = (float2*)(out + (size_t)m0 * D_DIM + d0);
                float2* o1 = (float2*)(out + (size_t)(m0 + 8) * D_DIM + d0);
                *o0 = make_float2(v00, v01);
                *o1 = make_float2(v10, v11);
            } else {
                float2* o0 = (float2*)(g_c + (size_t)m0 * D_DIM + d0);
                float2* o1 = (float2*)(g_c + (size_t)(m0 + 8) * D_DIM + d0);
                *o0 = make_float2(v00, v01);
                *o1 = make_float2(v10, v11);
            }
        }
    }
}

// ---------------------------------------------------------------------------
// In-place LayerNorm over D=1024, one block (256 threads, float4) per row.
// ---------------------------------------------------------------------------
__global__ void __launch_bounds__(256)
ln_kernel(float* __restrict__ x,
          const float* __restrict__ gamma,
          const float* __restrict__ beta)
{
    __shared__ float rs[8], rq[8];
    const int row = blockIdx.x;
    const int t = threadIdx.x;

    float4* xr = (float4*)(x + (size_t)row * D_DIM);
    float4 v = xr[t];

    float s = v.x + v.y + v.z + v.w;
    float q = v.x * v.x + v.y * v.y + v.z * v.z + v.w * v.w;

#pragma unroll
    for (int off = 16; off >= 1; off >>= 1) {
        s += __shfl_xor_sync(0xffffffffu, s, off);
        q += __shfl_xor_sync(0xffffffffu, q, off);
    }
    if ((t & 31) == 0) { rs[t >> 5] = s; rq[t >> 5] = q; }
    __syncthreads();

    s = 0.0f; q = 0.0f;
#pragma unroll
    for (int i = 0; i < 8; ++i) { s += rs[i]; q += rq[i]; }

    const float mean = s * (1.0f / D_DIM);
    const float var  = q * (1.0f / D_DIM) - mean * mean;
    const float rstd = rsqrtf(var + LN_EPS);

    const float4 gg = ((const float4*)gamma)[t];
    const float4 bb = ((const float4*)beta)[t];

    v.x = (v.x - mean) * rstd * gg.x + bb.x;
    v.y = (v.y - mean) * rstd * gg.y + bb.y;
    v.z = (v.z - mean) * rstd * gg.z + bb.z;
    v.w = (v.w - mean) * rstd * gg.w + bb.w;
    xr[t] = v;
}

// ---------------------------------------------------------------------------
// Launch: 3 kernels, same stream, graph-capturable, no allocations.
// ---------------------------------------------------------------------------
extern "C" void kernel_launch(void* const* d_in, const int* in_sizes, int n_in,
                              void* d_out, int out_size)
{
    const float* input  = (const float*)d_in[0];  // [B, N, 512]
    const float* statc  = (const float*)d_in[1];  // [N, 256]
    const float* W_feat = (const float*)d_in[2];  // [1024, 512]
    const float* b_feat = (const float*)d_in[3];  // [1024]
    const float* W_city = (const float*)d_in[4];  // [1024, 256]
    const float* b_city = (const float*)d_in[5];  // [1024]
    const float* gamma  = (const float*)d_in[6];  // [1024]
    const float* beta   = (const float*)d_in[7];  // [1024]
    float* out = (float*)d_out;                   // [B, N, 1024]

    // 1) city embed -> g_c   (K=256)
    gemm_tf32_kernel<K_DIM, false>
        <<<dim3(D_DIM / 128, N_DIM / 128), 256>>>(statc, W_city, b_city, nullptr);

    // 2) feat embed + leaky + gate -> out  (K=512)
    //    blockIdx.x = d-block (fast) so a wave of CTAs reuses input rows in L2.
    gemm_tf32_kernel<F_DIM, true>
        <<<dim3(D_DIM / 128, M_FEAT / 128), 256>>>(input, W_feat, b_feat, out);

    // 3) in-place LayerNorm on out
    ln_kernel<<<M_FEAT, 256>>>(out, gamma, beta);
}

// round 13
// speedup vs baseline: 1.1613x; 1.0401x over previous
#include <cuda_runtime.h>
#include <cstdint>

// Problem constants
#define B_DIM 32
#define N_DIM 2048
#define F_DIM 512          // NUM_FEATURE
#define K_DIM 256          // NUM_CLUSTER
#define D_DIM 1024         // D_MODEL
#define M_FEAT (B_DIM * N_DIM)   // 65536 rows for the big GEMM
#define LN_EPS 1e-5f
#define NEG_SLOPE 0.2f

// Static device scratch (no runtime allocation allowed)
__device__ uint32_t g_a[(size_t)M_FEAT * F_DIM];  // input pre-converted to tf32 (128 MB)
__device__ uint32_t g_w[(size_t)D_DIM * F_DIM];   // W_feat pre-converted to tf32 (2 MB)
__device__ float    g_c[(size_t)N_DIM * D_DIM];   // city embedding (8 MB)

// ---------------------------------------------------------------------------
// helpers
// ---------------------------------------------------------------------------
__device__ __forceinline__ uint32_t f2tf32(float x) {
    uint32_t y;
    asm("cvt.rna.tf32.f32 %0, %1;" : "=r"(y) : "f"(x));
    return y;
}

// m16n8k8 tf32 MMA (row.col)
__device__ __forceinline__ void mma_tf32_k8(float (&c)[4], const uint32_t (&a)[4],
                                            const uint32_t (&b)[2]) {
    asm volatile(
        "mma.sync.aligned.m16n8k8.row.col.f32.tf32.tf32.f32 "
        "{%0,%1,%2,%3}, {%4,%5,%6,%7}, {%8,%9}, {%0,%1,%2,%3};\n"
        : "+f"(c[0]), "+f"(c[1]), "+f"(c[2]), "+f"(c[3])
        : "r"(a[0]), "r"(a[1]), "r"(a[2]), "r"(a[3]), "r"(b[0]), "r"(b[1]));
}

__device__ __forceinline__ void cp16(uint32_t smem_dst, const uint32_t* gsrc) {
    asm volatile("cp.async.ca.shared.global [%0], [%1], 16;"
                 :: "r"(smem_dst), "l"((unsigned long long)__cvta_generic_to_global(gsrc)));
}
#define CP_COMMIT() asm volatile("cp.async.commit_group;" ::: "memory")
#define CP_WAIT2()  asm volatile("cp.async.wait_group 2;" ::: "memory")

// ---------------------------------------------------------------------------
// tf32 -> tf32-bits conversion pass (grid-stride over float4)
// ---------------------------------------------------------------------------
__global__ void __launch_bounds__(256)
cvt_kernel(const float* __restrict__ src, uint32_t* __restrict__ dst, int n4)
{
    int i = blockIdx.x * blockDim.x + threadIdx.x;
    if (i < n4) {
        float4 v = ((const float4*)src)[i];
        uint4 u;
        u.x = f2tf32(v.x); u.y = f2tf32(v.y); u.z = f2tf32(v.z); u.w = f2tf32(v.w);
        ((uint4*)dst)[i] = u;
    }
}

// ---------------------------------------------------------------------------
// Main GEMM (cp.async 4-stage pipeline, pre-converted tf32 operands):
//   out[m,d] = leaky( g_a[m,:] . g_w[d,:] + bias[d] ) * g_c[m % 2048][d]
// CTA tile 128(m) x 128(d), k16 stages, 256 threads = 8 warps of 64x32.
// ---------------------------------------------------------------------------
#define STAGES 4
#define LDK 20   // padded row stride (words): conflict-free for fragment loads
#define SA_WORDS (STAGES * 128 * LDK)
#define DYN_SMEM (2 * SA_WORDS * 4)   // A + B rings = 81920 B

__global__ void __launch_bounds__(256, 2)
feat_gemm_cp_kernel(const uint32_t* __restrict__ Aq,   // [65536, 512] tf32 bits
                    const uint32_t* __restrict__ Wq,   // [1024, 512] tf32 bits
                    const float* __restrict__ bias,    // [1024]
                    float* __restrict__ out)           // [65536, 1024]
{
    extern __shared__ uint32_t sm[];
    uint32_t* sA = sm;              // [STAGES][128][LDK]
    uint32_t* sB = sm + SA_WORDS;   // [STAGES][128][LDK]

    const int tid  = threadIdx.x;
    const int lane = tid & 31;
    const int warp = tid >> 5;
    const int wm   = warp & 1;   // m (x64)
    const int wn   = warp >> 1;  // d (x32)
    const int g    = lane >> 2;  // 0..7
    const int tig  = lane & 3;   // 0..3

    const int blockM = blockIdx.y * 128;
    const int blockN = blockIdx.x * 128;

    const uint32_t smA = (uint32_t)__cvta_generic_to_shared(sA);
    const uint32_t smB = (uint32_t)__cvta_generic_to_shared(sB);

    // chunk decomposition: per stage, A tile = 128 rows x 4 x 16B chunks (512),
    // each thread handles chunks {tid, tid+256}. Same for B.
    const int r0 = tid >> 2;         // 0..63
    const int r1 = r0 + 64;          // 64..127
    const int c4 = (tid & 3) * 4;    // word offset within row (0,4,8,12)

    const uint32_t* Ab0 = Aq + (size_t)(blockM + r0) * F_DIM + c4;
    const uint32_t* Ab1 = Aq + (size_t)(blockM + r1) * F_DIM + c4;
    const uint32_t* Wb0 = Wq + (size_t)(blockN + r0) * F_DIM + c4;
    const uint32_t* Wb1 = Wq + (size_t)(blockN + r1) * F_DIM + c4;

    auto issue_stage = [&](int kt) {
        const int st = kt & (STAGES - 1);
        const uint32_t dA = smA + (uint32_t)(((st * 128 + r0) * LDK + c4) * 4);
        const uint32_t dB = smB + (uint32_t)(((st * 128 + r0) * LDK + c4) * 4);
        const uint32_t rowAdv = (uint32_t)(64 * LDK * 4);
        cp16(dA,          Ab0 + kt * 16);
        cp16(dA + rowAdv, Ab1 + kt * 16);
        cp16(dB,          Wb0 + kt * 16);
        cp16(dB + rowAdv, Wb1 + kt * 16);
    };

    float acc[4][4][4];
#pragma unroll
    for (int mt = 0; mt < 4; ++mt)
#pragma unroll
        for (int nt = 0; nt < 4; ++nt)
#pragma unroll
            for (int i = 0; i < 4; ++i) acc[mt][nt][i] = 0.0f;

    const int KT = F_DIM / 16;   // 32

    // prologue: fill 3 stages
#pragma unroll
    for (int kt = 0; kt < STAGES - 1; ++kt) { issue_stage(kt); CP_COMMIT(); }

    for (int kt = 0; kt < KT; ++kt) {
        CP_WAIT2();          // with constant-rate commits, guarantees stage kt landed
        __syncthreads();     // make all threads' stage-kt data visible

        const int st = kt & (STAGES - 1);
        const uint32_t* As = sA + st * 128 * LDK;
        const uint32_t* Bs = sB + st * 128 * LDK;

#pragma unroll
        for (int ks = 0; ks < 2; ++ks) {      // two k8 groups per k16 stage
            const int k0 = ks * 8;
            uint32_t af[4][4];
#pragma unroll
            for (int mt = 0; mt < 4; ++mt) {
                const int r = wm * 64 + mt * 16 + g;
                af[mt][0] = As[r * LDK + k0 + tig];
                af[mt][1] = As[(r + 8) * LDK + k0 + tig];
                af[mt][2] = As[r * LDK + k0 + tig + 4];
                af[mt][3] = As[(r + 8) * LDK + k0 + tig + 4];
            }
            uint32_t bf[4][2];
#pragma unroll
            for (int nt = 0; nt < 4; ++nt) {
                const int rB = wn * 32 + nt * 8 + g;
                bf[nt][0] = Bs[rB * LDK + k0 + tig];
                bf[nt][1] = Bs[rB * LDK + k0 + tig + 4];
            }
#pragma unroll
            for (int mt = 0; mt < 4; ++mt)
#pragma unroll
                for (int nt = 0; nt < 4; ++nt)
                    mma_tf32_k8(acc[mt][nt], af[mt], bf[nt]);
        }

        // issue next stage (overwrites buffer consumed at iter kt-1; all warps
        // passed this iteration's __syncthreads, so it is free). Always commit
        // (possibly empty group) to keep the wait_group count constant.
        if (kt + STAGES - 1 < KT) issue_stage(kt + STAGES - 1);
        CP_COMMIT();
    }

    // Epilogue: bias + leaky + city gate, float2 stores
#pragma unroll
    for (int mt = 0; mt < 4; ++mt) {
        const int m0 = blockM + wm * 64 + mt * 16 + g;
#pragma unroll
        for (int nt = 0; nt < 4; ++nt) {
            const int d0 = blockN + wn * 32 + nt * 8 + 2 * tig;
            const float bs0 = bias[d0];
            const float bs1 = bias[d0 + 1];

            float v00 = acc[mt][nt][0] + bs0;
            float v01 = acc[mt][nt][1] + bs1;
            float v10 = acc[mt][nt][2] + bs0;
            float v11 = acc[mt][nt][3] + bs1;

            v00 = (v00 >= 0.0f) ? v00 : NEG_SLOPE * v00;
            v01 = (v01 >= 0.0f) ? v01 : NEG_SLOPE * v01;
            v10 = (v10 >= 0.0f) ? v10 : NEG_SLOPE * v10;
            v11 = (v11 >= 0.0f) ? v11 : NEG_SLOPE * v11;

            const float* gr0 = g_c + (size_t)(m0 & (N_DIM - 1)) * D_DIM;
            const float* gr1 = g_c + (size_t)((m0 + 8) & (N_DIM - 1)) * D_DIM;
            v00 *= gr0[d0]; v01 *= gr0[d0 + 1];
            v10 *= gr1[d0]; v11 *= gr1[d0 + 1];

            float2* o0 = (float2*)(out + (size_t)m0 * D_DIM + d0);
            float2* o1 = (float2*)(out + (size_t)(m0 + 8) * D_DIM + d0);
            *o0 = make_float2(v00, v01);
            *o1 = make_float2(v10, v11);
        }
    }
}

// ---------------------------------------------------------------------------
// City GEMM (register-staged m16n8k8; known-good from R12; writes g_c)
// ---------------------------------------------------------------------------
__global__ void __launch_bounds__(256, 2)
city_gemm_kernel(const float* __restrict__ A,
                 const float* __restrict__ W,
                 const float* __restrict__ bias)
{
    __shared__ uint32_t As[2][128][20];
    __shared__ uint32_t Bs[2][128][20];

    const int tid  = threadIdx.x;
    const int lane = tid & 31;
    const int warp = tid >> 5;
    const int wm   = warp & 1;
    const int wn   = warp >> 1;
    const int g    = lane >> 2;
    const int tig  = lane & 3;

    const int blockM = blockIdx.y * 128;
    const int blockN = blockIdx.x * 128;

    const int sr0 = tid >> 2;
    const int sc0 = (tid & 3) * 4;

    const float* Abase = A + (size_t)(blockM + sr0) * K_DIM + sc0;
    const float* Wbase = W + (size_t)(blockN + sr0) * K_DIM + sc0;

    float4 pa0, pa1, pb0, pb1;

    auto load_tile = [&](int kt) {
        const float* ap = Abase + kt * 16;
        const float* wp = Wbase + kt * 16;
        pa0 = *(const float4*)ap;
        pa1 = *(const float4*)(ap + (size_t)64 * K_DIM);
        pb0 = *(const float4*)wp;
        pb1 = *(const float4*)(wp + (size_t)64 * K_DIM);
    };
    auto store_tile = [&](int buf) {
        uint4 u;
        u.x = f2tf32(pa0.x); u.y = f2tf32(pa0.y); u.z = f2tf32(pa0.z); u.w = f2tf32(pa0.w);
        *(uint4*)&As[buf][sr0][sc0] = u;
        u.x = f2tf32(pa1.x); u.y = f2tf32(pa1.y); u.z = f2tf32(pa1.z); u.w = f2tf32(pa1.w);
        *(uint4*)&As[buf][sr0 + 64][sc0] = u;
        u.x = f2tf32(pb0.x); u.y = f2tf32(pb0.y); u.z = f2tf32(pb0.z); u.w = f2tf32(pb0.w);
        *(uint4*)&Bs[buf][sr0][sc0] = u;
        u.x = f2tf32(pb1.x); u.y = f2tf32(pb1.y); u.z = f2tf32(pb1.z); u.w = f2tf32(pb1.w);
        *(uint4*)&Bs[buf][sr0 + 64][sc0] = u;
    };

    float acc[4][4][4];
#pragma unroll
    for (int mt = 0; mt < 4; ++mt)
#pragma unroll
        for (int nt = 0; nt < 4; ++nt)
#pragma unroll
            for (int i = 0; i < 4; ++i) acc[mt][nt][i] = 0.0f;

    load_tile(0);
    store_tile(0);
    __syncthreads();

    const int KT = K_DIM / 16;
    for (int kt = 0; kt < KT; ++kt) {
        const int cur = kt & 1;
        if (kt + 1 < KT) load_tile(kt + 1);

#pragma unroll
        for (int ks = 0; ks < 2; ++ks) {
            const int k0 = ks * 8;
            uint32_t af[4][4];
#pragma unroll
            for (int mt = 0; mt < 4; ++mt) {
                const int r = wm * 64 + mt * 16 + g;
                af[mt][0] = As[cur][r][k0 + tig];
                af[mt][1] = As[cur][r + 8][k0 + tig];
                af[mt][2] = As[cur][r][k0 + tig + 4];
                af[mt][3] = As[cur][r + 8][k0 + tig + 4];
            }
            uint32_t bf[4][2];
#pragma unroll
            for (int nt = 0; nt < 4; ++nt) {
                const int rB = wn * 32 + nt * 8 + g;
                bf[nt][0] = Bs[cur][rB][k0 + tig];
                bf[nt][1] = Bs[cur][rB][k0 + tig + 4];
            }
#pragma unroll
            for (int mt = 0; mt < 4; ++mt)
#pragma unroll
                for (int nt = 0; nt < 4; ++nt)
                    mma_tf32_k8(acc[mt][nt], af[mt], bf[nt]);
        }

        if (kt + 1 < KT) store_tile(cur ^ 1);
        __syncthreads();
    }

#pragma unroll
    for (int mt = 0; mt < 4; ++mt) {
        const int m0 = blockM + wm * 64 + mt * 16 + g;
#pragma unroll
        for (int nt = 0; nt < 4; ++nt) {
            const int d0 = blockN + wn * 32 + nt * 8 + 2 * tig;
            const float bs0 = bias[d0];
            const float bs1 = bias[d0 + 1];
            float2* o0 = (float2*)(g_c + (size_t)m0 * D_DIM + d0);
            float2* o1 = (float2*)(g_c + (size_t)(m0 + 8) * D_DIM + d0);
            *o0 = make_float2(acc[mt][nt][0] + bs0, acc[mt][nt][1] + bs1);
            *o1 = make_float2(acc[mt][nt][2] + bs0, acc[mt][nt][3] + bs1);
        }
    }
}

// ---------------------------------------------------------------------------
// In-place LayerNorm over D=1024 — unchanged, known-good.
// ---------------------------------------------------------------------------
__global__ void __launch_bounds__(256)
ln_kernel(float* __restrict__ x,
          const float* __restrict__ gamma,
          const float* __restrict__ beta)
{
    __shared__ float rs[8], rq[8];
    const int row = blockIdx.x;
    const int t = threadIdx.x;

    float4* xr = (float4*)(x + (size_t)row * D_DIM);
    float4 v = xr[t];

    float s = v.x + v.y + v.z + v.w;
    float q = v.x * v.x + v.y * v.y + v.z * v.z + v.w * v.w;

#pragma unroll
    for (int off = 16; off >= 1; off >>= 1) {
        s += __shfl_xor_sync(0xffffffffu, s, off);
        q += __shfl_xor_sync(0xffffffffu, q, off);
    }
    if ((t & 31) == 0) { rs[t >> 5] = s; rq[t >> 5] = q; }
    __syncthreads();

    s = 0.0f; q = 0.0f;
#pragma unroll
    for (int i = 0; i < 8; ++i) { s += rs[i]; q += rq[i]; }

    const float mean = s * (1.0f / D_DIM);
    const float var  = q * (1.0f / D_DIM) - mean * mean;
    const float rstd = rsqrtf(var + LN_EPS);

    const float4 gg = ((const float4*)gamma)[t];
    const float4 bb = ((const float4*)beta)[t];

    v.x = (v.x - mean) * rstd * gg.x + bb.x;
    v.y = (v.y - mean) * rstd * gg.y + bb.y;
    v.z = (v.z - mean) * rstd * gg.z + bb.z;
    v.w = (v.w - mean) * rstd * gg.w + bb.w;
    xr[t] = v;
}

// ---------------------------------------------------------------------------
// Launch: 5 kernels, same stream, graph-capturable, no allocations.
// ---------------------------------------------------------------------------
extern "C" void kernel_launch(void* const* d_in, const int* in_sizes, int n_in,
                              void* d_out, int out_size)
{
    const float* input  = (const float*)d_in[0];  // [B, N, 512]
    const float* statc  = (const float*)d_in[1];  // [N, 256]
    const float* W_feat = (const float*)d_in[2];  // [1024, 512]
    const float* b_feat = (const float*)d_in[3];  // [1024]
    const float* W_city = (const float*)d_in[4];  // [1024, 256]
    const float* b_city = (const float*)d_in[5];  // [1024]
    const float* gamma  = (const float*)d_in[6];  // [1024]
    const float* beta   = (const float*)d_in[7];  // [1024]
    float* out = (float*)d_out;                   // [B, N, 1024]

    uint32_t* ga; cudaGetSymbolAddress((void**)&ga, g_a);
    uint32_t* gw; cudaGetSymbolAddress((void**)&gw, g_w);

    cudaFuncSetAttribute(feat_gemm_cp_kernel,
                         cudaFuncAttributeMaxDynamicSharedMemorySize, DYN_SMEM);

    // 0) pre-convert input and W_feat to tf32 bit patterns
    const int nA4 = M_FEAT * F_DIM / 4;   // 8,388,608
    const int nW4 = D_DIM * F_DIM / 4;    // 131,072
    cvt_kernel<<<(nA4 + 255) / 256, 256>>>(input, ga, nA4);
    cvt_kernel<<<(nW4 + 255) / 256, 256>>>(W_feat, gw, nW4);

    // 1) city embed -> g_c   (K=256)
    city_gemm_kernel<<<dim3(D_DIM / 128, N_DIM / 128), 256>>>(statc, W_city, b_city);

    // 2) feat embed + leaky + gate -> out (cp.async pipelined tf32 GEMM)
    feat_gemm_cp_kernel<<<dim3(D_DIM / 128, M_FEAT / 128), 256, DYN_SMEM>>>(
        ga, gw, b_feat, out);

    // 3) in-place LayerNorm on out
    ln_kernel<<<M_FEAT, 256>>>(out, gamma, beta);
}

// round 14
// speedup vs baseline: 1.1709x; 1.0083x over previous
#include <cuda_runtime.h>
#include <cstdint>

// Problem constants
#define B_DIM 32
#define N_DIM 2048
#define F_DIM 512          // NUM_FEATURE
#define K_DIM 256          // NUM_CLUSTER
#define D_DIM 1024         // D_MODEL
#define M_FEAT (B_DIM * N_DIM)   // 65536 rows for the big GEMM
#define LN_EPS 1e-5f
#define NEG_SLOPE 0.2f

// Static device scratch (no runtime allocation allowed)
__device__ uint32_t g_a[(size_t)M_FEAT * F_DIM];  // input pre-converted to tf32 (128 MB)
__device__ uint32_t g_w[(size_t)D_DIM * F_DIM];   // W_feat pre-converted to tf32 (2 MB)
__device__ float    g_c[(size_t)N_DIM * D_DIM];   // city embedding (8 MB)

// ---------------------------------------------------------------------------
// helpers
// ---------------------------------------------------------------------------
__device__ __forceinline__ uint32_t f2tf32(float x) {
    uint32_t y;
    asm("cvt.rna.tf32.f32 %0, %1;" : "=r"(y) : "f"(x));
    return y;
}

// m16n8k8 tf32 MMA (row.col)
__device__ __forceinline__ void mma_tf32_k8(float (&c)[4], const uint32_t (&a)[4],
                                            const uint32_t (&b)[2]) {
    asm volatile(
        "mma.sync.aligned.m16n8k8.row.col.f32.tf32.tf32.f32 "
        "{%0,%1,%2,%3}, {%4,%5,%6,%7}, {%8,%9}, {%0,%1,%2,%3};\n"
        : "+f"(c[0]), "+f"(c[1]), "+f"(c[2]), "+f"(c[3])
        : "r"(a[0]), "r"(a[1]), "r"(a[2]), "r"(a[3]), "r"(b[0]), "r"(b[1]));
}

__device__ __forceinline__ void cp16(uint32_t smem_dst, const uint32_t* gsrc) {
    asm volatile("cp.async.ca.shared.global [%0], [%1], 16;"
                 :: "r"(smem_dst), "l"((unsigned long long)__cvta_generic_to_global(gsrc)));
}
#define CP_COMMIT() asm volatile("cp.async.commit_group;" ::: "memory")
#define CP_WAIT2()  asm volatile("cp.async.wait_group 2;" ::: "memory")

// ---------------------------------------------------------------------------
// f32 -> tf32-bits conversion pass (one float4 per thread)
// ---------------------------------------------------------------------------
__global__ void __launch_bounds__(256)
cvt_kernel(const float* __restrict__ src, uint32_t* __restrict__ dst, int n4)
{
    int i = blockIdx.x * blockDim.x + threadIdx.x;
    if (i < n4) {
        float4 v = ((const float4*)src)[i];
        uint4 u;
        u.x = f2tf32(v.x); u.y = f2tf32(v.y); u.z = f2tf32(v.z); u.w = f2tf32(v.w);
        ((uint4*)dst)[i] = u;
    }
}

// ---------------------------------------------------------------------------
// Main GEMM (cp.async 4-stage pipeline, pre-converted tf32 operands):
//   out[m,d] = leaky( g_a[m,:] . g_w[d,:] + bias[d] ) * g_c[m % 2048][d]
// CTA tile 128(m) x 256(d), k16 stages, 256 threads = 8 warps of 64x64.
// 1 CTA/SM (reg-bound); crossbar bytes/FLOP cut ~1.45x vs 128x128.
// ---------------------------------------------------------------------------
#define BM 128
#define BN 256
#define STAGES 4
#define LDK 20   // padded row stride (words): conflict-free fragment pattern
#define SA_WORDS (STAGES * BM * LDK)          // 10240
#define SB_WORDS (STAGES * BN * LDK)          // 20480
#define DYN_SMEM ((SA_WORDS + SB_WORDS) * 4)  // 122880 B

__global__ void __launch_bounds__(256, 1)
feat_gemm_cp_kernel(const uint32_t* __restrict__ Aq,   // [65536, 512] tf32 bits
                    const uint32_t* __restrict__ Wq,   // [1024, 512] tf32 bits
                    const float* __restrict__ bias,    // [1024]
                    float* __restrict__ out)           // [65536, 1024]
{
    extern __shared__ uint32_t sm[];
    uint32_t* sA = sm;              // [STAGES][128][LDK]
    uint32_t* sB = sm + SA_WORDS;   // [STAGES][256][LDK]

    const int tid  = threadIdx.x;
    const int lane = tid & 31;
    const int warp = tid >> 5;
    const int wm   = warp & 1;   // m (x64)
    const int wn   = warp >> 1;  // d (x64), 0..3
    const int g    = lane >> 2;  // 0..7
    const int tig  = lane & 3;   // 0..3

    const int blockM = blockIdx.y * BM;
    const int blockN = blockIdx.x * BN;

    const uint32_t smA = (uint32_t)__cvta_generic_to_shared(sA);
    const uint32_t smB = (uint32_t)__cvta_generic_to_shared(sB);

    // chunk decomposition per stage:
    //   A: 128 rows x 4 x 16B chunks = 512 -> 2 per thread
    //   B: 256 rows x 4 x 16B chunks = 1024 -> 4 per thread
    const int r0 = tid >> 2;         // 0..63
    const int c4 = (tid & 3) * 4;    // word offset within row (0,4,8,12)

    const uint32_t* Ab = Aq + (size_t)(blockM + r0) * F_DIM + c4;
    const uint32_t* Wb = Wq + (size_t)(blockN + r0) * F_DIM + c4;

    auto issue_stage = [&](int kt) {
        const int st = kt & (STAGES - 1);
        const uint32_t rowAdv = (uint32_t)(64 * LDK * 4);
        uint32_t dA = smA + (uint32_t)(((st * BM + r0) * LDK + c4) * 4);
        cp16(dA,          Ab + kt * 16);
        cp16(dA + rowAdv, Ab + (size_t)64 * F_DIM + kt * 16);
        uint32_t dB = smB + (uint32_t)(((st * BN + r0) * LDK + c4) * 4);
#pragma unroll
        for (int j = 0; j < 4; ++j)
            cp16(dB + j * rowAdv, Wb + (size_t)(64 * j) * F_DIM + kt * 16);
    };

    float acc[4][8][4];
#pragma unroll
    for (int mt = 0; mt < 4; ++mt)
#pragma unroll
        for (int nt = 0; nt < 8; ++nt)
#pragma unroll
            for (int i = 0; i < 4; ++i) acc[mt][nt][i] = 0.0f;

    const int KT = F_DIM / 16;   // 32

    // prologue: fill 3 stages
#pragma unroll
    for (int kt = 0; kt < STAGES - 1; ++kt) { issue_stage(kt); CP_COMMIT(); }

    for (int kt = 0; kt < KT; ++kt) {
        CP_WAIT2();          // constant-rate commits => stage kt has landed
        __syncthreads();

        const int st = kt & (STAGES - 1);
        const uint32_t* As = sA + st * BM * LDK;
        const uint32_t* Bs = sB + st * BN * LDK;

#pragma unroll
        for (int ks = 0; ks < 2; ++ks) {      // two k8 groups per k16 stage
            const int k0 = ks * 8;
            uint32_t af[4][4];
#pragma unroll
            for (int mt = 0; mt < 4; ++mt) {
                const int r = wm * 64 + mt * 16 + g;
                af[mt][0] = As[r * LDK + k0 + tig];
                af[mt][1] = As[(r + 8) * LDK + k0 + tig];
                af[mt][2] = As[r * LDK + k0 + tig + 4];
                af[mt][3] = As[(r + 8) * LDK + k0 + tig + 4];
            }
            uint32_t bf[8][2];
#pragma unroll
            for (int nt = 0; nt < 8; ++nt) {
                const int rB = wn * 64 + nt * 8 + g;
                bf[nt][0] = Bs[rB * LDK + k0 + tig];
                bf[nt][1] = Bs[rB * LDK + k0 + tig + 4];
            }
#pragma unroll
            for (int mt = 0; mt < 4; ++mt)
#pragma unroll
                for (int nt = 0; nt < 8; ++nt)
                    mma_tf32_k8(acc[mt][nt], af[mt], bf[nt]);
        }

        // issue next stage; always commit (possibly empty) to keep count fixed
        if (kt + STAGES - 1 < KT) issue_stage(kt + STAGES - 1);
        CP_COMMIT();
    }

    // Epilogue: bias + leaky + city gate, float2 stores
#pragma unroll
    for (int mt = 0; mt < 4; ++mt) {
        const int m0 = blockM + wm * 64 + mt * 16 + g;
        const float* gr0 = g_c + (size_t)(m0 & (N_DIM - 1)) * D_DIM;
        const float* gr1 = g_c + (size_t)((m0 + 8) & (N_DIM - 1)) * D_DIM;
        float* or0 = out + (size_t)m0 * D_DIM;
        float* or1 = out + (size_t)(m0 + 8) * D_DIM;
#pragma unroll
        for (int nt = 0; nt < 8; ++nt) {
            const int d0 = blockN + wn * 64 + nt * 8 + 2 * tig;
            const float bs0 = bias[d0];
            const float bs1 = bias[d0 + 1];

            float v00 = acc[mt][nt][0] + bs0;
            float v01 = acc[mt][nt][1] + bs1;
            float v10 = acc[mt][nt][2] + bs0;
            float v11 = acc[mt][nt][3] + bs1;

            v00 = (v00 >= 0.0f) ? v00 : NEG_SLOPE * v00;
            v01 = (v01 >= 0.0f) ? v01 : NEG_SLOPE * v01;
            v10 = (v10 >= 0.0f) ? v10 : NEG_SLOPE * v10;
            v11 = (v11 >= 0.0f) ? v11 : NEG_SLOPE * v11;

            v00 *= gr0[d0]; v01 *= gr0[d0 + 1];
            v10 *= gr1[d0]; v11 *= gr1[d0 + 1];

            *(float2*)(or0 + d0) = make_float2(v00, v01);
            *(float2*)(or1 + d0) = make_float2(v10, v11);
        }
    }
}

// ---------------------------------------------------------------------------
// City GEMM (register-staged m16n8k8; known-good; writes g_c)
// ---------------------------------------------------------------------------
__global__ void __launch_bounds__(256, 2)
city_gemm_kernel(const float* __restrict__ A,
                 const float* __restrict__ W,
                 const float* __restrict__ bias)
{
    __shared__ uint32_t As[2][128][20];
    __shared__ uint32_t Bs[2][128][20];

    const int tid  = threadIdx.x;
    const int lane = tid & 31;
    const int warp = tid >> 5;
    const int wm   = warp & 1;
    const int wn   = warp >> 1;
    const int g    = lane >> 2;
    const int tig  = lane & 3;

    const int blockM = blockIdx.y * 128;
    const int blockN = blockIdx.x * 128;

    const int sr0 = tid >> 2;
    const int sc0 = (tid & 3) * 4;

    const float* Abase = A + (size_t)(blockM + sr0) * K_DIM + sc0;
    const float* Wbase = W + (size_t)(blockN + sr0) * K_DIM + sc0;

    float4 pa0, pa1, pb0, pb1;

    auto load_tile = [&](int kt) {
        const float* ap = Abase + kt * 16;
        const float* wp = Wbase + kt * 16;
        pa0 = *(const float4*)ap;
        pa1 = *(const float4*)(ap + (size_t)64 * K_DIM);
        pb0 = *(const float4*)wp;
        pb1 = *(const float4*)(wp + (size_t)64 * K_DIM);
    };
    auto store_tile = [&](int buf) {
        uint4 u;
        u.x = f2tf32(pa0.x); u.y = f2tf32(pa0.y); u.z = f2tf32(pa0.z); u.w = f2tf32(pa0.w);
        *(uint4*)&As[buf][sr0][sc0] = u;
        u.x = f2tf32(pa1.x); u.y = f2tf32(pa1.y); u.z = f2tf32(pa1.z); u.w = f2tf32(pa1.w);
        *(uint4*)&As[buf][sr0 + 64][sc0] = u;
        u.x = f2tf32(pb0.x); u.y = f2tf32(pb0.y); u.z = f2tf32(pb0.z); u.w = f2tf32(pb0.w);
        *(uint4*)&Bs[buf][sr0][sc0] = u;
        u.x = f2tf32(pb1.x); u.y = f2tf32(pb1.y); u.z = f2tf32(pb1.z); u.w = f2tf32(pb1.w);
        *(uint4*)&Bs[buf][sr0 + 64][sc0] = u;
    };

    float acc[4][4][4];
#pragma unroll
    for (int mt = 0; mt < 4; ++mt)
#pragma unroll
        for (int nt = 0; nt < 4; ++nt)
#pragma unroll
            for (int i = 0; i < 4; ++i) acc[mt][nt][i] = 0.0f;

    load_tile(0);
    store_tile(0);
    __syncthreads();

    const int KT = K_DIM / 16;
    for (int kt = 0; kt < KT; ++kt) {
        const int cur = kt & 1;
        if (kt + 1 < KT) load_tile(kt + 1);

#pragma unroll
        for (int ks = 0; ks < 2; ++ks) {
            const int k0 = ks * 8;
            uint32_t af[4][4];
#pragma unroll
            for (int mt = 0; mt < 4; ++mt) {
                const int r = wm * 64 + mt * 16 + g;
                af[mt][0] = As[cur][r][k0 + tig];
                af[mt][1] = As[cur][r + 8][k0 + tig];
                af[mt][2] = As[cur][r][k0 + tig + 4];
                af[mt][3] = As[cur][r + 8][k0 + tig + 4];
            }
            uint32_t bf[4][2];
#pragma unroll
            for (int nt = 0; nt < 4; ++nt) {
                const int rB = wn * 32 + nt * 8 + g;
                bf[nt][0] = Bs[cur][rB][k0 + tig];
                bf[nt][1] = Bs[cur][rB][k0 + tig + 4];
            }
#pragma unroll
            for (int mt = 0; mt < 4; ++mt)
#pragma unroll
                for (int nt = 0; nt < 4; ++nt)
                    mma_tf32_k8(acc[mt][nt], af[mt], bf[nt]);
        }

        if (kt + 1 < KT) store_tile(cur ^ 1);
        __syncthreads();
    }

#pragma unroll
    for (int mt = 0; mt < 4; ++mt) {
        const int m0 = blockM + wm * 64 + mt * 16 + g;
#pragma unroll
        for (int nt = 0; nt < 4; ++nt) {
            const int d0 = blockN + wn * 32 + nt * 8 + 2 * tig;
            const float bs0 = bias[d0];
            const float bs1 = bias[d0 + 1];
            float2* o0 = (float2*)(g_c + (size_t)m0 * D_DIM + d0);
            float2* o1 = (float2*)(g_c + (size_t)(m0 + 8) * D_DIM + d0);
            *o0 = make_float2(acc[mt][nt][0] + bs0, acc[mt][nt][1] + bs1);
            *o1 = make_float2(acc[mt][nt][2] + bs0, acc[mt][nt][3] + bs1);
        }
    }
}

// ---------------------------------------------------------------------------
// In-place LayerNorm over D=1024 — unchanged, known-good.
// ---------------------------------------------------------------------------
__global__ void __launch_bounds__(256)
ln_kernel(float* __restrict__ x,
          const float* __restrict__ gamma,
          const float* __restrict__ beta)
{
    __shared__ float rs[8], rq[8];
    const int row = blockIdx.x;
    const int t = threadIdx.x;

    float4* xr = (float4*)(x + (size_t)row * D_DIM);
    float4 v = xr[t];

    float s = v.x + v.y + v.z + v.w;
    float q = v.x * v.x + v.y * v.y + v.z * v.z + v.w * v.w;

#pragma unroll
    for (int off = 16; off >= 1; off >>= 1) {
        s += __shfl_xor_sync(0xffffffffu, s, off);
        q += __shfl_xor_sync(0xffffffffu, q, off);
    }
    if ((t & 31) == 0) { rs[t >> 5] = s; rq[t >> 5] = q; }
    __syncthreads();

    s = 0.0f; q = 0.0f;
#pragma unroll
    for (int i = 0; i < 8; ++i) { s += rs[i]; q += rq[i]; }

    const float mean = s * (1.0f / D_DIM);
    const float var  = q * (1.0f / D_DIM) - mean * mean;
    const float rstd = rsqrtf(var + LN_EPS);

    const float4 gg = ((const float4*)gamma)[t];
    const float4 bb = ((const float4*)beta)[t];

    v.x = (v.x - mean) * rstd * gg.x + bb.x;
    v.y = (v.y - mean) * rstd * gg.y + bb.y;
    v.z = (v.z - mean) * rstd * gg.z + bb.z;
    v.w = (v.w - mean) * rstd * gg.w + bb.w;
    xr[t] = v;
}

// ---------------------------------------------------------------------------
// Launch: 5 kernels, same stream, graph-capturable, no allocations.
// ---------------------------------------------------------------------------
extern "C" void kernel_launch(void* const* d_in, const int* in_sizes, int n_in,
                              void* d_out, int out_size)
{
    const float* input  = (const float*)d_in[0];  // [B, N, 512]
    const float* statc  = (const float*)d_in[1];  // [N, 256]
    const float* W_feat = (const float*)d_in[2];  // [1024, 512]
    const float* b_feat = (const float*)d_in[3];  // [1024]
    const float* W_city = (const float*)d_in[4];  // [1024, 256]
    const float* b_city = (const float*)d_in[5];  // [1024]
    const float* gamma  = (const float*)d_in[6];  // [1024]
    const float* beta   = (const float*)d_in[7];  // [1024]
    float* out = (float*)d_out;                   // [B, N, 1024]

    uint32_t* ga; cudaGetSymbolAddress((void**)&ga, g_a);
    uint32_t* gw; cudaGetSymbolAddress((void**)&gw, g_w);

    cudaFuncSetAttribute(feat_gemm_cp_kernel,
                         cudaFuncAttributeMaxDynamicSharedMemorySize, DYN_SMEM);

    // 0) pre-convert input and W_feat to tf32 bit patterns
    const int nA4 = M_FEAT * F_DIM / 4;   // 8,388,608
    const int nW4 = D_DIM * F_DIM / 4;    // 131,072
    cvt_kernel<<<(nA4 + 255) / 256, 256>>>(input, ga, nA4);
    cvt_kernel<<<(nW4 + 255) / 256, 256>>>(W_feat, gw, nW4);

    // 1) city embed -> g_c   (K=256)
    city_gemm_kernel<<<dim3(D_DIM / 128, N_DIM / 128), 256>>>(statc, W_city, b_city);

    // 2) feat embed + leaky + gate -> out (cp.async pipelined tf32 GEMM)
    feat_gemm_cp_kernel<<<dim3(D_DIM / BN, M_FEAT / BM), 256, DYN_SMEM>>>(
        ga, gw, b_feat, out);

    // 3) in-place LayerNorm on out
    ln_kernel<<<M_FEAT, 256>>>(out, gamma, beta);
}

// round 16
// speedup vs baseline: 1.6903x; 1.4436x over previous
#include <cuda_runtime.h>
#include <cuda_fp16.h>
#include <cstdint>

// Problem constants
#define B_DIM 32
#define N_DIM 2048
#define F_DIM 512          // NUM_FEATURE
#define FW    (F_DIM / 2)  // fp16 row stride in 32-bit words (256)
#define K_DIM 256          // NUM_CLUSTER
#define D_DIM 1024         // D_MODEL
#define M_FEAT (B_DIM * N_DIM)   // 65536 rows for the big GEMM
#define LN_EPS 1e-5f
#define NEG_SLOPE 0.2f

// Static device scratch (no runtime allocation allowed)
__device__ uint32_t g_a[(size_t)M_FEAT * FW];   // input as packed fp16 (64 MB)
__device__ uint32_t g_w[(size_t)D_DIM * FW];    // W_feat as packed fp16 (1 MB)
__device__ float    g_c[(size_t)N_DIM * D_DIM]; // city embedding (8 MB)

// ---------------------------------------------------------------------------
// helpers
// ---------------------------------------------------------------------------
__device__ __forceinline__ uint32_t f2tf32(float x) {
    uint32_t y;
    asm("cvt.rna.tf32.f32 %0, %1;" : "=r"(y) : "f"(x));
    return y;
}

// fp16 m16n8k16 MMA (row.col), f32 accumulate.
// Word-level fragment addressing identical to tf32 k8 (word = 2 halves):
//   a0=W[g][tig] a1=W[g+8][tig] a2=W[g][tig+4] a3=W[g+8][tig+4]
//   b0=W[n=g][tig] b1=W[g][tig+4]
//   c0=(g,2tig) c1=(g,2tig+1) c2=(g+8,2tig) c3=(g+8,2tig+1)
__device__ __forceinline__ void mma_f16_k16(float (&c)[4], const uint32_t (&a)[4],
                                            const uint32_t (&b)[2]) {
    asm volatile(
        "mma.sync.aligned.m16n8k16.row.col.f32.f16.f16.f32 "
        "{%0,%1,%2,%3}, {%4,%5,%6,%7}, {%8,%9}, {%0,%1,%2,%3};\n"
        : "+f"(c[0]), "+f"(c[1]), "+f"(c[2]), "+f"(c[3])
        : "r"(a[0]), "r"(a[1]), "r"(a[2]), "r"(a[3]), "r"(b[0]), "r"(b[1]));
}

// tf32 m16n8k8 MMA (city GEMM, known-good)
__device__ __forceinline__ void mma_tf32_k8(float (&c)[4], const uint32_t (&a)[4],
                                            const uint32_t (&b)[2]) {
    asm volatile(
        "mma.sync.aligned.m16n8k8.row.col.f32.tf32.tf32.f32 "
        "{%0,%1,%2,%3}, {%4,%5,%6,%7}, {%8,%9}, {%0,%1,%2,%3};\n"
        : "+f"(c[0]), "+f"(c[1]), "+f"(c[2]), "+f"(c[3])
        : "r"(a[0]), "r"(a[1]), "r"(a[2]), "r"(a[3]), "r"(b[0]), "r"(b[1]));
}

__device__ __forceinline__ void cp16(uint32_t smem_dst, const uint32_t* gsrc) {
    asm volatile("cp.async.ca.shared.global [%0], [%1], 16;"
                 :: "r"(smem_dst), "l"((unsigned long long)__cvta_generic_to_global(gsrc)));
}
#define CP_COMMIT() asm volatile("cp.async.commit_group;" ::: "memory")
#define CP_WAIT2()  asm volatile("cp.async.wait_group 2;" ::: "memory")

// ---------------------------------------------------------------------------
// f32 -> packed fp16 conversion (8 floats -> 4 half2 words per thread)
// ---------------------------------------------------------------------------
__global__ void __launch_bounds__(256)
cvt_fp16_kernel(const float* __restrict__ src, uint32_t* __restrict__ dst, int n8)
{
    int i = blockIdx.x * blockDim.x + threadIdx.x;
    if (i < n8) {
        float4 v0 = ((const float4*)src)[2 * i];
        float4 v1 = ((const float4*)src)[2 * i + 1];
        __half2 h0 = __floats2half2_rn(v0.x, v0.y);
        __half2 h1 = __floats2half2_rn(v0.z, v0.w);
        __half2 h2 = __floats2half2_rn(v1.x, v1.y);
        __half2 h3 = __floats2half2_rn(v1.z, v1.w);
        uint4 u;
        u.x = *(uint32_t*)&h0;
        u.y = *(uint32_t*)&h1;
        u.z = *(uint32_t*)&h2;
        u.w = *(uint32_t*)&h3;
        ((uint4*)dst)[i] = u;
    }
}

// ---------------------------------------------------------------------------
// Main GEMM (cp.async 4-stage pipeline, packed fp16 operands):
//   out[m,d] = leaky( g_a[m,:] . g_w[d,:] + bias[d] ) * g_c[m % 2048][d]
// CTA tile 128(m) x 256(d), k32 stages (16 words), 256 threads = 8 warps 64x64.
// ---------------------------------------------------------------------------
#define BM 128
#define BN 256
#define STAGES 4
#define LDK 20   // padded row stride (words): conflict-free fragment pattern
#define SA_WORDS (STAGES * BM * LDK)          // 10240
#define SB_WORDS (STAGES * BN * LDK)          // 20480
#define DYN_SMEM ((SA_WORDS + SB_WORDS) * 4)  // 122880 B

__global__ void __launch_bounds__(256, 1)
feat_gemm_cp_kernel(const uint32_t* __restrict__ Aq,   // [65536, 256] half2 words
                    const uint32_t* __restrict__ Wq,   // [1024, 256] half2 words
                    const float* __restrict__ bias,    // [1024]
                    float* __restrict__ out)           // [65536, 1024]
{
    extern __shared__ uint32_t sm[];
    uint32_t* sA = sm;              // [STAGES][128][LDK]
    uint32_t* sB = sm + SA_WORDS;   // [STAGES][256][LDK]

    const int tid  = threadIdx.x;
    const int lane = tid & 31;
    const int warp = tid >> 5;
    const int wm   = warp & 1;   // m (x64)
    const int wn   = warp >> 1;  // d (x64), 0..3
    const int g    = lane >> 2;  // 0..7
    const int tig  = lane & 3;   // 0..3

    const int blockM = blockIdx.y * BM;
    const int blockN = blockIdx.x * BN;

    const uint32_t smA = (uint32_t)__cvta_generic_to_shared(sA);
    const uint32_t smB = (uint32_t)__cvta_generic_to_shared(sB);

    // per stage (k32 = 16 words/row):
    //   A: 128 rows x 4 x 16B chunks = 512 -> 2 per thread
    //   B: 256 rows x 4 x 16B chunks = 1024 -> 4 per thread
    const int r0 = tid >> 2;         // 0..63
    const int c4 = (tid & 3) * 4;    // word offset within stage row (0,4,8,12)

    const uint32_t* Ab = Aq + (size_t)(blockM + r0) * FW + c4;
    const uint32_t* Wb = Wq + (size_t)(blockN + r0) * FW + c4;

    auto issue_stage = [&](int kt) {
        const int st = kt & (STAGES - 1);
        const uint32_t rowAdv = (uint32_t)(64 * LDK * 4);
        uint32_t dA = smA + (uint32_t)(((st * BM + r0) * LDK + c4) * 4);
        cp16(dA,          Ab + kt * 16);
        cp16(dA + rowAdv, Ab + (size_t)64 * FW + kt * 16);
        uint32_t dB = smB + (uint32_t)(((st * BN + r0) * LDK + c4) * 4);
#pragma unroll
        for (int j = 0; j < 4; ++j)
            cp16(dB + j * rowAdv, Wb + (size_t)(64 * j) * FW + kt * 16);
    };

    float acc[4][8][4];
#pragma unroll
    for (int mt = 0; mt < 4; ++mt)
#pragma unroll
        for (int nt = 0; nt < 8; ++nt)
#pragma unroll
            for (int i = 0; i < 4; ++i) acc[mt][nt][i] = 0.0f;

    const int KT = F_DIM / 32;   // 16 stages of k32

    // prologue: fill 3 stages
#pragma unroll
    for (int kt = 0; kt < STAGES - 1; ++kt) { issue_stage(kt); CP_COMMIT(); }

    for (int kt = 0; kt < KT; ++kt) {
        CP_WAIT2();          // constant-rate commits => stage kt has landed
        __syncthreads();

        const int st = kt & (STAGES - 1);
        const uint32_t* As = sA + st * BM * LDK;
        const uint32_t* Bs = sB + st * BN * LDK;

#pragma unroll
        for (int ks = 0; ks < 2; ++ks) {      // two k16 groups per k32 stage
            const int k0 = ks * 8;            // word offset
            uint32_t af[4][4];
#pragma unroll
            for (int mt = 0; mt < 4; ++mt) {
                const int r = wm * 64 + mt * 16 + g;
                af[mt][0] = As[r * LDK + k0 + tig];
                af[mt][1] = As[(r + 8) * LDK + k0 + tig];
                af[mt][2] = As[r * LDK + k0 + tig + 4];
                af[mt][3] = As[(r + 8) * LDK + k0 + tig + 4];
            }
            uint32_t bf[8][2];
#pragma unroll
            for (int nt = 0; nt < 8; ++nt) {
                const int rB = wn * 64 + nt * 8 + g;
                bf[nt][0] = Bs[rB * LDK + k0 + tig];
                bf[nt][1] = Bs[rB * LDK + k0 + tig + 4];
            }
#pragma unroll
            for (int mt = 0; mt < 4; ++mt)
#pragma unroll
                for (int nt = 0; nt < 8; ++nt)
                    mma_f16_k16(acc[mt][nt], af[mt], bf[nt]);
        }

        // issue next stage; always commit (possibly empty) to keep count fixed
        if (kt + STAGES - 1 < KT) issue_stage(kt + STAGES - 1);
        CP_COMMIT();
    }

    // Epilogue: bias + leaky + city gate, float2 stores
#pragma unroll
    for (int mt = 0; mt < 4; ++mt) {
        const int m0 = blockM + wm * 64 + mt * 16 + g;
        const float* gr0 = g_c + (size_t)(m0 & (N_DIM - 1)) * D_DIM;
        const float* gr1 = g_c + (size_t)((m0 + 8) & (N_DIM - 1)) * D_DIM;
        float* or0 = out + (size_t)m0 * D_DIM;
        float* or1 = out + (size_t)(m0 + 8) * D_DIM;
#pragma unroll
        for (int nt = 0; nt < 8; ++nt) {
            const int d0 = blockN + wn * 64 + nt * 8 + 2 * tig;
            const float bs0 = bias[d0];
            const float bs1 = bias[d0 + 1];

            float v00 = acc[mt][nt][0] + bs0;
            float v01 = acc[mt][nt][1] + bs1;
            float v10 = acc[mt][nt][2] + bs0;
            float v11 = acc[mt][nt][3] + bs1;

            v00 = (v00 >= 0.0f) ? v00 : NEG_SLOPE * v00;
            v01 = (v01 >= 0.0f) ? v01 : NEG_SLOPE * v01;
            v10 = (v10 >= 0.0f) ? v10 : NEG_SLOPE * v10;
            v11 = (v11 >= 0.0f) ? v11 : NEG_SLOPE * v11;

            v00 *= gr0[d0]; v01 *= gr0[d0 + 1];
            v10 *= gr1[d0]; v11 *= gr1[d0 + 1];

            *(float2*)(or0 + d0) = make_float2(v00, v01);
            *(float2*)(or1 + d0) = make_float2(v10, v11);
        }
    }
}

// ---------------------------------------------------------------------------
// City GEMM (register-staged tf32 m16n8k8; known-good; writes g_c)
// ---------------------------------------------------------------------------
__global__ void __launch_bounds__(256, 2)
city_gemm_kernel(const float* __restrict__ A,
                 const float* __restrict__ W,
                 const float* __restrict__ bias)
{
    __shared__ uint32_t As[2][128][20];
    __shared__ uint32_t Bs[2][128][20];

    const int tid  = threadIdx.x;
    const int lane = tid & 31;
    const int warp = tid >> 5;
    const int wm   = warp & 1;
    const int wn   = warp >> 1;
    const int g    = lane >> 2;
    const int tig  = lane & 3;

    const int blockM = blockIdx.y * 128;
    const int blockN = blockIdx.x * 128;

    const int sr0 = tid >> 2;
    const int sc0 = (tid & 3) * 4;

    const float* Abase = A + (size_t)(blockM + sr0) * K_DIM + sc0;
    const float* Wbase = W + (size_t)(blockN + sr0) * K_DIM + sc0;

    float4 pa0, pa1, pb0, pb1;

    auto load_tile = [&](int kt) {
        const float* ap = Abase + kt * 16;
        const float* wp = Wbase + kt * 16;
        pa0 = *(const float4*)ap;
        pa1 = *(const float4*)(ap + (size_t)64 * K_DIM);
        pb0 = *(const float4*)wp;
        pb1 = *(const float4*)(wp + (size_t)64 * K_DIM);
    };
    auto store_tile = [&](int buf) {
        uint4 u;
        u.x = f2tf32(pa0.x); u.y = f2tf32(pa0.y); u.z = f2tf32(pa0.z); u.w = f2tf32(pa0.w);
        *(uint4*)&As[buf][sr0][sc0] = u;
        u.x = f2tf32(pa1.x); u.y = f2tf32(pa1.y); u.z = f2tf32(pa1.z); u.w = f2tf32(pa1.w);
        *(uint4*)&As[buf][sr0 + 64][sc0] = u;
        u.x = f2tf32(pb0.x); u.y = f2tf32(pb0.y); u.z = f2tf32(pb0.z); u.w = f2tf32(pb0.w);
        *(uint4*)&Bs[buf][sr0][sc0] = u;
        u.x = f2tf32(pb1.x); u.y = f2tf32(pb1.y); u.z = f2tf32(pb1.z); u.w = f2tf32(pb1.w);
        *(uint4*)&Bs[buf][sr0 + 64][sc0] = u;
    };

    float acc[4][4][4];
#pragma unroll
    for (int mt = 0; mt < 4; ++mt)
#pragma unroll
        for (int nt = 0; nt < 4; ++nt)
#pragma unroll
            for (int i = 0; i < 4; ++i) acc[mt][nt][i] = 0.0f;

    load_tile(0);
    store_tile(0);
    __syncthreads();

    const int KT = K_DIM / 16;
    for (int kt = 0; kt < KT; ++kt) {
        const int cur = kt & 1;
        if (kt + 1 < KT) load_tile(kt + 1);

#pragma unroll
        for (int ks = 0; ks < 2; ++ks) {
            const int k0 = ks * 8;
            uint32_t af[4][4];
#pragma unroll
            for (int mt = 0; mt < 4; ++mt) {
                const int r = wm * 64 + mt * 16 + g;
                af[mt][0] = As[cur][r][k0 + tig];
                af[mt][1] = As[cur][r + 8][k0 + tig];
                af[mt][2] = As[cur][r][k0 + tig + 4];
                af[mt][3] = As[cur][r + 8][k0 + tig + 4];
            }
            uint32_t bf[4][2];
#pragma unroll
            for (int nt = 0; nt < 4; ++nt) {
                const int rB = wn * 32 + nt * 8 + g;
                bf[nt][0] = Bs[cur][rB][k0 + tig];
                bf[nt][1] = Bs[cur][rB][k0 + tig + 4];
            }
#pragma unroll
            for (int mt = 0; mt < 4; ++mt)
#pragma unroll
                for (int nt = 0; nt < 4; ++nt)
                    mma_tf32_k8(acc[mt][nt], af[mt], bf[nt]);
        }

        if (kt + 1 < KT) store_tile(cur ^ 1);
        __syncthreads();
    }

#pragma unroll
    for (int mt = 0; mt < 4; ++mt) {
        const int m0 = blockM + wm * 64 + mt * 16 + g;
#pragma unroll
        for (int nt = 0; nt < 4; ++nt) {
            const int d0 = blockN + wn * 32 + nt * 8 + 2 * tig;
            const float bs0 = bias[d0];
            const float bs1 = bias[d0 + 1];
            float2* o0 = (float2*)(g_c + (size_t)m0 * D_DIM + d0);
            float2* o1 = (float2*)(g_c + (size_t)(m0 + 8) * D_DIM + d0);
            *o0 = make_float2(acc[mt][nt][0] + bs0, acc[mt][nt][1] + bs1);
            *o1 = make_float2(acc[mt][nt][2] + bs0, acc[mt][nt][3] + bs1);
        }
    }
}

// ---------------------------------------------------------------------------
// In-place LayerNorm over D=1024 — unchanged, known-good.
// ---------------------------------------------------------------------------
__global__ void __launch_bounds__(256)
ln_kernel(float* __restrict__ x,
          const float* __restrict__ gamma,
          const float* __restrict__ beta)
{
    __shared__ float rs[8], rq[8];
    const int row = blockIdx.x;
    const int t = threadIdx.x;

    float4* xr = (float4*)(x + (size_t)row * D_DIM);
    float4 v = xr[t];

    float s = v.x + v.y + v.z + v.w;
    float q = v.x * v.x + v.y * v.y + v.z * v.z + v.w * v.w;

#pragma unroll
    for (int off = 16; off >= 1; off >>= 1) {
        s += __shfl_xor_sync(0xffffffffu, s, off);
        q += __shfl_xor_sync(0xffffffffu, q, off);
    }
    if ((t & 31) == 0) { rs[t >> 5] = s; rq[t >> 5] = q; }
    __syncthreads();

    s = 0.0f; q = 0.0f;
#pragma unroll
    for (int i = 0; i < 8; ++i) { s += rs[i]; q += rq[i]; }

    const float mean = s * (1.0f / D_DIM);
    const float var  = q * (1.0f / D_DIM) - mean * mean;
    const float rstd = rsqrtf(var + LN_EPS);

    const float4 gg = ((const float4*)gamma)[t];
    const float4 bb = ((const float4*)beta)[t];

    v.x = (v.x - mean) * rstd * gg.x + bb.x;
    v.y = (v.y - mean) * rstd * gg.y + bb.y;
    v.z = (v.z - mean) * rstd * gg.z + bb.z;
    v.w = (v.w - mean) * rstd * gg.w + bb.w;
    xr[t] = v;
}

// ---------------------------------------------------------------------------
// Launch: 5 kernels, same stream, graph-capturable, no allocations.
// ---------------------------------------------------------------------------
extern "C" void kernel_launch(void* const* d_in, const int* in_sizes, int n_in,
                              void* d_out, int out_size)
{
    const float* input  = (const float*)d_in[0];  // [B, N, 512]
    const float* statc  = (const float*)d_in[1];  // [N, 256]
    const float* W_feat = (const float*)d_in[2];  // [1024, 512]
    const float* b_feat = (const float*)d_in[3];  // [1024]
    const float* W_city = (const float*)d_in[4];  // [1024, 256]
    const float* b_city = (const float*)d_in[5];  // [1024]
    const float* gamma  = (const float*)d_in[6];  // [1024]
    const float* beta   = (const float*)d_in[7];  // [1024]
    float* out = (float*)d_out;                   // [B, N, 1024]

    uint32_t* ga; cudaGetSymbolAddress((void**)&ga, g_a);
    uint32_t* gw; cudaGetSymbolAddress((void**)&gw, g_w);

    cudaFuncSetAttribute(feat_gemm_cp_kernel,
                         cudaFuncAttributeMaxDynamicSharedMemorySize, DYN_SMEM);

    // 0) pre-convert input and W_feat to packed fp16
    const int nA8 = M_FEAT * F_DIM / 8;   // 4,194,304
    const int nW8 = D_DIM * F_DIM / 8;    // 65,536
    cvt_fp16_kernel<<<(nA8 + 255) / 256, 256>>>(input, ga, nA8);
    cvt_fp16_kernel<<<(nW8 + 255) / 256, 256>>>(W_feat, gw, nW8);

    // 1) city embed -> g_c   (K=256, tf32)
    city_gemm_kernel<<<dim3(D_DIM / 128, N_DIM / 128), 256>>>(statc, W_city, b_city);

    // 2) feat embed + leaky + gate -> out (cp.async pipelined fp16 GEMM)
    feat_gemm_cp_kernel<<<dim3(D_DIM / BN, M_FEAT / BM), 256, DYN_SMEM>>>(
        ga, gw, b_feat, out);

    // 3) in-place LayerNorm on out
    ln_kernel<<<M_FEAT, 256>>>(out, gamma, beta);
}

// round 17
// speedup vs baseline: 1.6947x; 1.0026x over previous
#include <cuda_runtime.h>
#include <cuda_fp16.h>
#include <cstdint>

// Problem constants
#define B_DIM 32
#define N_DIM 2048
#define F_DIM 512          // NUM_FEATURE
#define FW    (F_DIM / 2)  // fp16 row stride in 32-bit words (256)
#define K_DIM 256          // NUM_CLUSTER
#define D_DIM 1024         // D_MODEL
#define M_FEAT (B_DIM * N_DIM)   // 65536 rows for the big GEMM
#define LN_EPS 1e-5f
#define NEG_SLOPE 0.2f

// Static device scratch (no runtime allocation allowed)
__device__ uint32_t g_a[(size_t)M_FEAT * FW];   // input as packed fp16 (64 MB)
__device__ uint32_t g_w[(size_t)D_DIM * FW];    // W_feat as packed fp16 (1 MB)
__device__ float    g_c[(size_t)N_DIM * D_DIM]; // city embedding (8 MB)

// ---------------------------------------------------------------------------
// helpers
// ---------------------------------------------------------------------------
__device__ __forceinline__ uint32_t f2tf32(float x) {
    uint32_t y;
    asm("cvt.rna.tf32.f32 %0, %1;" : "=r"(y) : "f"(x));
    return y;
}

// fp16 m16n8k16 MMA (row.col), f32 accumulate.
// Word-level fragment addressing identical to tf32 k8 (word = 2 halves):
//   a0=W[g][tig] a1=W[g+8][tig] a2=W[g][tig+4] a3=W[g+8][tig+4]
//   b0=W[n=g][tig] b1=W[g][tig+4]
//   c0=(g,2tig) c1=(g,2tig+1) c2=(g+8,2tig) c3=(g+8,2tig+1)
__device__ __forceinline__ void mma_f16_k16(float (&c)[4], const uint32_t (&a)[4],
                                            const uint32_t (&b)[2]) {
    asm volatile(
        "mma.sync.aligned.m16n8k16.row.col.f32.f16.f16.f32 "
        "{%0,%1,%2,%3}, {%4,%5,%6,%7}, {%8,%9}, {%0,%1,%2,%3};\n"
        : "+f"(c[0]), "+f"(c[1]), "+f"(c[2]), "+f"(c[3])
        : "r"(a[0]), "r"(a[1]), "r"(a[2]), "r"(a[3]), "r"(b[0]), "r"(b[1]));
}

// tf32 m16n8k8 MMA (city GEMM, known-good)
__device__ __forceinline__ void mma_tf32_k8(float (&c)[4], const uint32_t (&a)[4],
                                            const uint32_t (&b)[2]) {
    asm volatile(
        "mma.sync.aligned.m16n8k8.row.col.f32.tf32.tf32.f32 "
        "{%0,%1,%2,%3}, {%4,%5,%6,%7}, {%8,%9}, {%0,%1,%2,%3};\n"
        : "+f"(c[0]), "+f"(c[1]), "+f"(c[2]), "+f"(c[3])
        : "r"(a[0]), "r"(a[1]), "r"(a[2]), "r"(a[3]), "r"(b[0]), "r"(b[1]));
}

__device__ __forceinline__ void cp16(uint32_t smem_dst, const uint32_t* gsrc) {
    asm volatile("cp.async.ca.shared.global [%0], [%1], 16;"
                 :: "r"(smem_dst), "l"((unsigned long long)__cvta_generic_to_global(gsrc)));
}
#define CP_COMMIT() asm volatile("cp.async.commit_group;" ::: "memory")
#define CP_WAIT2()  asm volatile("cp.async.wait_group 2;" ::: "memory")

// ---------------------------------------------------------------------------
// f32 -> packed fp16 conversion (8 floats -> 4 half2 words per thread)
// ---------------------------------------------------------------------------
__global__ void __launch_bounds__(256)
cvt_fp16_kernel(const float* __restrict__ src, uint32_t* __restrict__ dst, int n8)
{
    int i = blockIdx.x * blockDim.x + threadIdx.x;
    if (i < n8) {
        float4 v0 = ((const float4*)src)[2 * i];
        float4 v1 = ((const float4*)src)[2 * i + 1];
        __half2 h0 = __floats2half2_rn(v0.x, v0.y);
        __half2 h1 = __floats2half2_rn(v0.z, v0.w);
        __half2 h2 = __floats2half2_rn(v1.x, v1.y);
        __half2 h3 = __floats2half2_rn(v1.z, v1.w);
        uint4 u;
        u.x = *(uint32_t*)&h0;
        u.y = *(uint32_t*)&h1;
        u.z = *(uint32_t*)&h2;
        u.w = *(uint32_t*)&h3;
        ((uint4*)dst)[i] = u;
    }
}

// ---------------------------------------------------------------------------
// Main GEMM (cp.async 4-stage pipeline, packed fp16 operands):
//   out[m,d] = leaky( g_a[m,:] . g_w[d,:] + bias[d] ) * g_c[m % 2048][d]
// CTA tile 128(m) x 256(d), k32 stages (16 words), 256 threads = 8 warps 64x64.
// ---------------------------------------------------------------------------
#define BM 128
#define BN 256
#define STAGES 4
#define LDK 20   // padded row stride (words): conflict-free fragment pattern
#define SA_WORDS (STAGES * BM * LDK)          // 10240
#define SB_WORDS (STAGES * BN * LDK)          // 20480
#define DYN_SMEM ((SA_WORDS + SB_WORDS) * 4)  // 122880 B

__global__ void __launch_bounds__(256, 1)
feat_gemm_cp_kernel(const uint32_t* __restrict__ Aq,   // [65536, 256] half2 words
                    const uint32_t* __restrict__ Wq,   // [1024, 256] half2 words
                    const float* __restrict__ bias,    // [1024]
                    float* __restrict__ out)           // [65536, 1024]
{
    extern __shared__ uint32_t sm[];
    uint32_t* sA = sm;              // [STAGES][128][LDK]
    uint32_t* sB = sm + SA_WORDS;   // [STAGES][256][LDK]

    const int tid  = threadIdx.x;
    const int lane = tid & 31;
    const int warp = tid >> 5;
    const int wm   = warp & 1;   // m (x64)
    const int wn   = warp >> 1;  // d (x64), 0..3
    const int g    = lane >> 2;  // 0..7
    const int tig  = lane & 3;   // 0..3

    const int blockM = blockIdx.y * BM;
    const int blockN = blockIdx.x * BN;

    const uint32_t smA = (uint32_t)__cvta_generic_to_shared(sA);
    const uint32_t smB = (uint32_t)__cvta_generic_to_shared(sB);

    // per stage (k32 = 16 words/row):
    //   A: 128 rows x 4 x 16B chunks = 512 -> 2 per thread
    //   B: 256 rows x 4 x 16B chunks = 1024 -> 4 per thread
    const int r0 = tid >> 2;         // 0..63
    const int c4 = (tid & 3) * 4;    // word offset within stage row (0,4,8,12)

    const uint32_t* Ab = Aq + (size_t)(blockM + r0) * FW + c4;
    const uint32_t* Wb = Wq + (size_t)(blockN + r0) * FW + c4;

    auto issue_stage = [&](int kt) {
        const int st = kt & (STAGES - 1);
        const uint32_t rowAdv = (uint32_t)(64 * LDK * 4);
        uint32_t dA = smA + (uint32_t)(((st * BM + r0) * LDK + c4) * 4);
        cp16(dA,          Ab + kt * 16);
        cp16(dA + rowAdv, Ab + (size_t)64 * FW + kt * 16);
        uint32_t dB = smB + (uint32_t)(((st * BN + r0) * LDK + c4) * 4);
#pragma unroll
        for (int j = 0; j < 4; ++j)
            cp16(dB + j * rowAdv, Wb + (size_t)(64 * j) * FW + kt * 16);
    };

    float acc[4][8][4];
#pragma unroll
    for (int mt = 0; mt < 4; ++mt)
#pragma unroll
        for (int nt = 0; nt < 8; ++nt)
#pragma unroll
            for (int i = 0; i < 4; ++i) acc[mt][nt][i] = 0.0f;

    const int KT = F_DIM / 32;   // 16 stages of k32

    // prologue: fill 3 stages
#pragma unroll
    for (int kt = 0; kt < STAGES - 1; ++kt) { issue_stage(kt); CP_COMMIT(); }

    for (int kt = 0; kt < KT; ++kt) {
        CP_WAIT2();          // constant-rate commits => stage kt has landed
        __syncthreads();

        const int st = kt & (STAGES - 1);
        const uint32_t* As = sA + st * BM * LDK;
        const uint32_t* Bs = sB + st * BN * LDK;

#pragma unroll
        for (int ks = 0; ks < 2; ++ks) {      // two k16 groups per k32 stage
            const int k0 = ks * 8;            // word offset
            uint32_t af[4][4];
#pragma unroll
            for (int mt = 0; mt < 4; ++mt) {
                const int r = wm * 64 + mt * 16 + g;
                af[mt][0] = As[r * LDK + k0 + tig];
                af[mt][1] = As[(r + 8) * LDK + k0 + tig];
                af[mt][2] = As[r * LDK + k0 + tig + 4];
                af[mt][3] = As[(r + 8) * LDK + k0 + tig + 4];
            }
            uint32_t bf[8][2];
#pragma unroll
            for (int nt = 0; nt < 8; ++nt) {
                const int rB = wn * 64 + nt * 8 + g;
                bf[nt][0] = Bs[rB * LDK + k0 + tig];
                bf[nt][1] = Bs[rB * LDK + k0 + tig + 4];
            }
#pragma unroll
            for (int mt = 0; mt < 4; ++mt)
#pragma unroll
                for (int nt = 0; nt < 8; ++nt)
                    mma_f16_k16(acc[mt][nt], af[mt], bf[nt]);
        }

        // issue next stage; always commit (possibly empty) to keep count fixed
        if (kt + STAGES - 1 < KT) issue_stage(kt + STAGES - 1);
        CP_COMMIT();
    }

    // Epilogue: bias + leaky + city gate, float2 stores
#pragma unroll
    for (int mt = 0; mt < 4; ++mt) {
        const int m0 = blockM + wm * 64 + mt * 16 + g;
        const float* gr0 = g_c + (size_t)(m0 & (N_DIM - 1)) * D_DIM;
        const float* gr1 = g_c + (size_t)((m0 + 8) & (N_DIM - 1)) * D_DIM;
        float* or0 = out + (size_t)m0 * D_DIM;
        float* or1 = out + (size_t)(m0 + 8) * D_DIM;
#pragma unroll
        for (int nt = 0; nt < 8; ++nt) {
            const int d0 = blockN + wn * 64 + nt * 8 + 2 * tig;
            const float bs0 = bias[d0];
            const float bs1 = bias[d0 + 1];

            float v00 = acc[mt][nt][0] + bs0;
            float v01 = acc[mt][nt][1] + bs1;
            float v10 = acc[mt][nt][2] + bs0;
            float v11 = acc[mt][nt][3] + bs1;

            v00 = (v00 >= 0.0f) ? v00 : NEG_SLOPE * v00;
            v01 = (v01 >= 0.0f) ? v01 : NEG_SLOPE * v01;
            v10 = (v10 >= 0.0f) ? v10 : NEG_SLOPE * v10;
            v11 = (v11 >= 0.0f) ? v11 : NEG_SLOPE * v11;

            v00 *= gr0[d0]; v01 *= gr0[d0 + 1];
            v10 *= gr1[d0]; v11 *= gr1[d0 + 1];

            *(float2*)(or0 + d0) = make_float2(v00, v01);
            *(float2*)(or1 + d0) = make_float2(v10, v11);
        }
    }
}

// ---------------------------------------------------------------------------
// City GEMM (register-staged tf32 m16n8k8; known-good; writes g_c)
// ---------------------------------------------------------------------------
__global__ void __launch_bounds__(256, 2)
city_gemm_kernel(const float* __restrict__ A,
                 const float* __restrict__ W,
                 const float* __restrict__ bias)
{
    __shared__ uint32_t As[2][128][20];
    __shared__ uint32_t Bs[2][128][20];

    const int tid  = threadIdx.x;
    const int lane = tid & 31;
    const int warp = tid >> 5;
    const int wm   = warp & 1;
    const int wn   = warp >> 1;
    const int g    = lane >> 2;
    const int tig  = lane & 3;

    const int blockM = blockIdx.y * 128;
    const int blockN = blockIdx.x * 128;

    const int sr0 = tid >> 2;
    const int sc0 = (tid & 3) * 4;

    const float* Abase = A + (size_t)(blockM + sr0) * K_DIM + sc0;
    const float* Wbase = W + (size_t)(blockN + sr0) * K_DIM + sc0;

    float4 pa0, pa1, pb0, pb1;

    auto load_tile = [&](int kt) {
        const float* ap = Abase + kt * 16;
        const float* wp = Wbase + kt * 16;
        pa0 = *(const float4*)ap;
        pa1 = *(const float4*)(ap + (size_t)64 * K_DIM);
        pb0 = *(const float4*)wp;
        pb1 = *(const float4*)(wp + (size_t)64 * K_DIM);
    };
    auto store_tile = [&](int buf) {
        uint4 u;
        u.x = f2tf32(pa0.x); u.y = f2tf32(pa0.y); u.z = f2tf32(pa0.z); u.w = f2tf32(pa0.w);
        *(uint4*)&As[buf][sr0][sc0] = u;
        u.x = f2tf32(pa1.x); u.y = f2tf32(pa1.y); u.z = f2tf32(pa1.z); u.w = f2tf32(pa1.w);
        *(uint4*)&As[buf][sr0 + 64][sc0] = u;
        u.x = f2tf32(pb0.x); u.y = f2tf32(pb0.y); u.z = f2tf32(pb0.z); u.w = f2tf32(pb0.w);
        *(uint4*)&Bs[buf][sr0][sc0] = u;
        u.x = f2tf32(pb1.x); u.y = f2tf32(pb1.y); u.z = f2tf32(pb1.z); u.w = f2tf32(pb1.w);
        *(uint4*)&Bs[buf][sr0 + 64][sc0] = u;
    };

    float acc[4][4][4];
#pragma unroll
    for (int mt = 0; mt < 4; ++mt)
#pragma unroll
        for (int nt = 0; nt < 4; ++nt)
#pragma unroll
            for (int i = 0; i < 4; ++i) acc[mt][nt][i] = 0.0f;

    load_tile(0);
    store_tile(0);
    __syncthreads();

    const int KT = K_DIM / 16;
    for (int kt = 0; kt < KT; ++kt) {
        const int cur = kt & 1;
        if (kt + 1 < KT) load_tile(kt + 1);

#pragma unroll
        for (int ks = 0; ks < 2; ++ks) {
            const int k0 = ks * 8;
            uint32_t af[4][4];
#pragma unroll
            for (int mt = 0; mt < 4; ++mt) {
                const int r = wm * 64 + mt * 16 + g;
                af[mt][0] = As[cur][r][k0 + tig];
                af[mt][1] = As[cur][r + 8][k0 + tig];
                af[mt][2] = As[cur][r][k0 + tig + 4];
                af[mt][3] = As[cur][r + 8][k0 + tig + 4];
            }
            uint32_t bf[4][2];
#pragma unroll
            for (int nt = 0; nt < 4; ++nt) {
                const int rB = wn * 32 + nt * 8 + g;
                bf[nt][0] = Bs[cur][rB][k0 + tig];
                bf[nt][1] = Bs[cur][rB][k0 + tig + 4];
            }
#pragma unroll
            for (int mt = 0; mt < 4; ++mt)
#pragma unroll
                for (int nt = 0; nt < 4; ++nt)
                    mma_tf32_k8(acc[mt][nt], af[mt], bf[nt]);
        }

        if (kt + 1 < KT) store_tile(cur ^ 1);
        __syncthreads();
    }

#pragma unroll
    for (int mt = 0; mt < 4; ++mt) {
        const int m0 = blockM + wm * 64 + mt * 16 + g;
#pragma unroll
        for (int nt = 0; nt < 4; ++nt) {
            const int d0 = blockN + wn * 32 + nt * 8 + 2 * tig;
            const float bs0 = bias[d0];
            const float bs1 = bias[d0 + 1];
            float2* o0 = (float2*)(g_c + (size_t)m0 * D_DIM + d0);
            float2* o1 = (float2*)(g_c + (size_t)(m0 + 8) * D_DIM + d0);
            *o0 = make_float2(acc[mt][nt][0] + bs0, acc[mt][nt][1] + bs1);
            *o1 = make_float2(acc[mt][nt][2] + bs0, acc[mt][nt][3] + bs1);
        }
    }
}

// ---------------------------------------------------------------------------
// In-place LayerNorm over D=1024 — unchanged, known-good.
// ---------------------------------------------------------------------------
__global__ void __launch_bounds__(256)
ln_kernel(float* __restrict__ x,
          const float* __restrict__ gamma,
          const float* __restrict__ beta)
{
    __shared__ float rs[8], rq[8];
    const int row = blockIdx.x;
    const int t = threadIdx.x;

    float4* xr = (float4*)(x + (size_t)row * D_DIM);
    float4 v = xr[t];

    float s = v.x + v.y + v.z + v.w;
    float q = v.x * v.x + v.y * v.y + v.z * v.z + v.w * v.w;

#pragma unroll
    for (int off = 16; off >= 1; off >>= 1) {
        s += __shfl_xor_sync(0xffffffffu, s, off);
        q += __shfl_xor_sync(0xffffffffu, q, off);
    }
    if ((t & 31) == 0) { rs[t >> 5] = s; rq[t >> 5] = q; }
    __syncthreads();

    s = 0.0f; q = 0.0f;
#pragma unroll
    for (int i = 0; i < 8; ++i) { s += rs[i]; q += rq[i]; }

    const float mean = s * (1.0f / D_DIM);
    const float var  = q * (1.0f / D_DIM) - mean * mean;
    const float rstd = rsqrtf(var + LN_EPS);

    const float4 gg = ((const float4*)gamma)[t];
    const float4 bb = ((const float4*)beta)[t];

    v.x = (v.x - mean) * rstd * gg.x + bb.x;
    v.y = (v.y - mean) * rstd * gg.y + bb.y;
    v.z = (v.z - mean) * rstd * gg.z + bb.z;
    v.w = (v.w - mean) * rstd * gg.w + bb.w;
    xr[t] = v;
}

// ---------------------------------------------------------------------------
// Launch: 5 kernels, same stream, graph-capturable, no allocations.
// ---------------------------------------------------------------------------
extern "C" void kernel_launch(void* const* d_in, const int* in_sizes, int n_in,
                              void* d_out, int out_size)
{
    const float* input  = (const float*)d_in[0];  // [B, N, 512]
    const float* statc  = (const float*)d_in[1];  // [N, 256]
    const float* W_feat = (const float*)d_in[2];  // [1024, 512]
    const float* b_feat = (const float*)d_in[3];  // [1024]
    const float* W_city = (const float*)d_in[4];  // [1024, 256]
    const float* b_city = (const float*)d_in[5];  // [1024]
    const float* gamma  = (const float*)d_in[6];  // [1024]
    const float* beta   = (const float*)d_in[7];  // [1024]
    float* out = (float*)d_out;                   // [B, N, 1024]

    uint32_t* ga; cudaGetSymbolAddress((void**)&ga, g_a);
    uint32_t* gw; cudaGetSymbolAddress((void**)&gw, g_w);

    cudaFuncSetAttribute(feat_gemm_cp_kernel,
                         cudaFuncAttributeMaxDynamicSharedMemorySize, DYN_SMEM);

    // 0) pre-convert input and W_feat to packed fp16
    const int nA8 = M_FEAT * F_DIM / 8;   // 4,194,304
    const int nW8 = D_DIM * F_DIM / 8;    // 65,536
    cvt_fp16_kernel<<<(nA8 + 255) / 256, 256>>>(input, ga, nA8);
    cvt_fp16_kernel<<<(nW8 + 255) / 256, 256>>>(W_feat, gw, nW8);

    // 1) city embed -> g_c   (K=256, tf32)
    city_gemm_kernel<<<dim3(D_DIM / 128, N_DIM / 128), 256>>>(statc, W_city, b_city);

    // 2) feat embed + leaky + gate -> out (cp.async pipelined fp16 GEMM)
    feat_gemm_cp_kernel<<<dim3(D_DIM / BN, M_FEAT / BM), 256, DYN_SMEM>>>(
        ga, gw, b_feat, out);

    // 3) in-place LayerNorm on out
    ln_kernel<<<M_FEAT, 256>>>(out, gamma, beta);
}